// round 2
// baseline (speedup 1.0000x reference)
#include <cuda_runtime.h>
#include <math.h>

#define BB   2
#define SS   2048
#define EE   1024
#define E3   3072
#define HH   16
#define DH   64

// Scratch (allocation-free rule: __device__ globals)
__device__ float g_qkv [BB * SS * E3];   // [B*S, 3E]
__device__ float g_attn[BB * SS * EE];   // [B*S, E]

// ---------------------------------------------------------------------------
// Generic SGEMM with bias: C[M,N] = A[M,K] @ Bw[N,K]^T + bias[N]
// BM=BN=64, BK=16, 256 threads, 4x4 micro-tile per thread.
// ---------------------------------------------------------------------------
__global__ __launch_bounds__(256) void gemm_bias_kernel(
    const float* __restrict__ A, const float* __restrict__ Bw,
    const float* __restrict__ bias, float* __restrict__ C,
    int M, int N, int K)
{
    __shared__ float As[16][64];   // [k][m]
    __shared__ float Bs[16][64];   // [k][n]

    const int tid = threadIdx.x;
    const int tx = tid & 15;       // 0..15 -> n
    const int ty = tid >> 4;       // 0..15 -> m
    const int row0 = blockIdx.y * 64;
    const int col0 = blockIdx.x * 64;

    // loader: each thread one float4 per tile per operand
    const int lr = tid >> 2;          // 0..63 (row within tile)
    const int lc = (tid & 3) * 4;     // 0,4,8,12 (k within tile)

    const float* Aload = A + (size_t)(row0 + lr) * K + lc;
    const float* Bload = Bw + (size_t)(col0 + lr) * K + lc;

    float acc[4][4] = {};

    for (int k0 = 0; k0 < K; k0 += 16) {
        float4 av = *(const float4*)(Aload + k0);
        float4 bv = *(const float4*)(Bload + k0);
        As[lc + 0][lr] = av.x; As[lc + 1][lr] = av.y;
        As[lc + 2][lr] = av.z; As[lc + 3][lr] = av.w;
        Bs[lc + 0][lr] = bv.x; Bs[lc + 1][lr] = bv.y;
        Bs[lc + 2][lr] = bv.z; Bs[lc + 3][lr] = bv.w;
        __syncthreads();

        #pragma unroll
        for (int kk = 0; kk < 16; kk++) {
            float4 a = *(const float4*)&As[kk][ty * 4];
            float4 b = *(const float4*)&Bs[kk][tx * 4];
            acc[0][0] += a.x * b.x; acc[0][1] += a.x * b.y;
            acc[0][2] += a.x * b.z; acc[0][3] += a.x * b.w;
            acc[1][0] += a.y * b.x; acc[1][1] += a.y * b.y;
            acc[1][2] += a.y * b.z; acc[1][3] += a.y * b.w;
            acc[2][0] += a.z * b.x; acc[2][1] += a.z * b.y;
            acc[2][2] += a.z * b.z; acc[2][3] += a.z * b.w;
            acc[3][0] += a.w * b.x; acc[3][1] += a.w * b.y;
            acc[3][2] += a.w * b.z; acc[3][3] += a.w * b.w;
        }
        __syncthreads();
    }

    // epilogue: add bias, float4 stores
    float4 bvec = *(const float4*)&bias[col0 + tx * 4];
    #pragma unroll
    for (int i = 0; i < 4; i++) {
        float4 o;
        o.x = acc[i][0] + bvec.x;
        o.y = acc[i][1] + bvec.y;
        o.z = acc[i][2] + bvec.z;
        o.w = acc[i][3] + bvec.w;
        *(float4*)&C[(size_t)(row0 + ty * 4 + i) * N + col0 + tx * 4] = o;
    }
}

// ---------------------------------------------------------------------------
// Flash attention (fp32, online softmax).
// One block = one (b, h, q-tile of 64). 256 threads, 4x4 micro-tiles.
// Qs,Ks stored [d][idx]; Vs stored [k][d]; P reuses Ks buffer as [q][k].
// ---------------------------------------------------------------------------
__global__ __launch_bounds__(256) void attn_kernel(float* __restrict__ out)
{
    __shared__ float Qs[64][64];   // [d][q]
    __shared__ float Ks[64][64];   // [d][k]; reused as P[q][k]
    __shared__ float Vs[64][64];   // [k][d]

    const int tid = threadIdx.x;
    const int tx = tid & 15;   // key col group / out-dim group
    const int ty = tid >> 4;   // query row group
    const int qt = blockIdx.x;
    const int h  = blockIdx.y;
    const int b  = blockIdx.z;

    const float* qkv = g_qkv;
    const size_t rowstride = E3;
    const size_t qbase = (size_t)(b * SS + qt * 64) * rowstride + h * DH;

    // Load Q tile transposed: conflict-free stores (row varies across warp).
    #pragma unroll
    for (int it = 0; it < 4; it++) {
        int f = it * 256 + tid;          // float4 id 0..1023
        int r  = f & 63;                 // tile row
        int c4 = (f >> 6) * 4;           // d offset
        float4 v = *(const float4*)&qkv[qbase + (size_t)r * rowstride + c4];
        Qs[c4 + 0][r] = v.x; Qs[c4 + 1][r] = v.y;
        Qs[c4 + 2][r] = v.z; Qs[c4 + 3][r] = v.w;
    }

    float m[4], l[4], accO[4][4] = {};
    #pragma unroll
    for (int i = 0; i < 4; i++) { m[i] = -1e30f; l[i] = 0.0f; }

    const float scale = 0.125f;   // 1/sqrt(64)

    for (int kt = 0; kt < SS / 64; kt++) {
        __syncthreads();   // prev iteration done reading Ks(P)/Vs

        const size_t kbase = (size_t)(b * SS + kt * 64) * rowstride + EE  + h * DH;
        const size_t vbase = (size_t)(b * SS + kt * 64) * rowstride + 2 * EE + h * DH;
        #pragma unroll
        for (int it = 0; it < 4; it++) {
            int f = it * 256 + tid;
            // K transposed
            int r  = f & 63;
            int c4 = (f >> 6) * 4;
            float4 kv = *(const float4*)&qkv[kbase + (size_t)r * rowstride + c4];
            Ks[c4 + 0][r] = kv.x; Ks[c4 + 1][r] = kv.y;
            Ks[c4 + 2][r] = kv.z; Ks[c4 + 3][r] = kv.w;
            // V natural (coalesced)
            int vr  = f >> 4;
            int vc4 = (f & 15) * 4;
            float4 vv = *(const float4*)&qkv[vbase + (size_t)vr * rowstride + vc4];
            *(float4*)&Vs[vr][vc4] = vv;
        }
        __syncthreads();

        // S = Q K^T  (K-dim = 64)
        float sacc[4][4] = {};
        #pragma unroll 16
        for (int kk = 0; kk < 64; kk++) {
            float4 a = *(const float4*)&Qs[kk][ty * 4];
            float4 c = *(const float4*)&Ks[kk][tx * 4];
            sacc[0][0] += a.x * c.x; sacc[0][1] += a.x * c.y;
            sacc[0][2] += a.x * c.z; sacc[0][3] += a.x * c.w;
            sacc[1][0] += a.y * c.x; sacc[1][1] += a.y * c.y;
            sacc[1][2] += a.y * c.z; sacc[1][3] += a.y * c.w;
            sacc[2][0] += a.z * c.x; sacc[2][1] += a.z * c.y;
            sacc[2][2] += a.z * c.z; sacc[2][3] += a.z * c.w;
            sacc[3][0] += a.w * c.x; sacc[3][1] += a.w * c.y;
            sacc[3][2] += a.w * c.z; sacc[3][3] += a.w * c.w;
        }

        // online softmax per row (row owned by 16-lane groups; xor-shfl 8,4,2,1
        // stays within each 16-lane half of the warp)
        float p[4][4];
        #pragma unroll
        for (int i = 0; i < 4; i++) {
            float s0 = sacc[i][0] * scale, s1 = sacc[i][1] * scale;
            float s2 = sacc[i][2] * scale, s3 = sacc[i][3] * scale;
            float mx = fmaxf(fmaxf(s0, s1), fmaxf(s2, s3));
            #pragma unroll
            for (int off = 8; off >= 1; off >>= 1)
                mx = fmaxf(mx, __shfl_xor_sync(0xffffffffu, mx, off));
            float mnew = fmaxf(m[i], mx);
            float corr = __expf(m[i] - mnew);
            p[i][0] = __expf(s0 - mnew);
            p[i][1] = __expf(s1 - mnew);
            p[i][2] = __expf(s2 - mnew);
            p[i][3] = __expf(s3 - mnew);
            float rs = p[i][0] + p[i][1] + p[i][2] + p[i][3];
            #pragma unroll
            for (int off = 8; off >= 1; off >>= 1)
                rs += __shfl_xor_sync(0xffffffffu, rs, off);
            l[i] = l[i] * corr + rs;
            m[i] = mnew;
            accO[i][0] *= corr; accO[i][1] *= corr;
            accO[i][2] *= corr; accO[i][3] *= corr;
        }

        __syncthreads();   // everyone done reading Ks

        // write P into Ks buffer as [q][k], float4 along k
        #pragma unroll
        for (int i = 0; i < 4; i++) {
            float4 pv = make_float4(p[i][0], p[i][1], p[i][2], p[i][3]);
            *(float4*)&Ks[ty * 4 + i][tx * 4] = pv;
        }
        __syncthreads();

        // O += P @ V
        #pragma unroll 16
        for (int kk = 0; kk < 64; kk++) {
            float a0 = Ks[ty * 4 + 0][kk];
            float a1 = Ks[ty * 4 + 1][kk];
            float a2 = Ks[ty * 4 + 2][kk];
            float a3 = Ks[ty * 4 + 3][kk];
            float4 v = *(const float4*)&Vs[kk][tx * 4];
            accO[0][0] += a0 * v.x; accO[0][1] += a0 * v.y;
            accO[0][2] += a0 * v.z; accO[0][3] += a0 * v.w;
            accO[1][0] += a1 * v.x; accO[1][1] += a1 * v.y;
            accO[1][2] += a1 * v.z; accO[1][3] += a1 * v.w;
            accO[2][0] += a2 * v.x; accO[2][1] += a2 * v.y;
            accO[2][2] += a2 * v.z; accO[2][3] += a2 * v.w;
            accO[3][0] += a3 * v.x; accO[3][1] += a3 * v.y;
            accO[3][2] += a3 * v.z; accO[3][3] += a3 * v.w;
        }
    }

    // epilogue: divide by l, write [B,S,E] with column h*64 + tx*4
    #pragma unroll
    for (int i = 0; i < 4; i++) {
        float inv = 1.0f / l[i];
        float4 o;
        o.x = accO[i][0] * inv; o.y = accO[i][1] * inv;
        o.z = accO[i][2] * inv; o.w = accO[i][3] * inv;
        size_t row = (size_t)(b * SS + qt * 64 + ty * 4 + i);
        *(float4*)&out[row * EE + h * DH + tx * 4] = o;
    }
}

extern "C" void kernel_launch(void* const* d_in, const int* in_sizes, int n_in,
                              void* d_out, int out_size)
{
    const float* x     = (const float*)d_in[0];
    const float* w_in  = (const float*)d_in[1];
    const float* b_in  = (const float*)d_in[2];
    const float* w_out = (const float*)d_in[3];
    const float* b_out = (const float*)d_in[4];
    float* out = (float*)d_out;

    float* qkv  = nullptr;
    float* attn = nullptr;
    cudaGetSymbolAddress((void**)&qkv,  g_qkv);
    cudaGetSymbolAddress((void**)&attn, g_attn);

    const int M = BB * SS;   // 4096

    // 1) QKV projection: [4096,3072] = x[4096,1024] @ w_in[3072,1024]^T + b_in
    gemm_bias_kernel<<<dim3(E3 / 64, M / 64), 256>>>(x, w_in, b_in, qkv, M, E3, EE);

    // 2) attention per (q-tile, head, batch)
    attn_kernel<<<dim3(SS / 64, HH, BB), 256>>>(attn);

    // 3) output projection: out[4096,1024] = attn @ w_out[1024,1024]^T + b_out
    gemm_bias_kernel<<<dim3(EE / 64, M / 64), 256>>>(attn, w_out, b_out, out, M, EE, EE);
}

// round 4
// speedup vs baseline: 1.4118x; 1.4118x over previous
#include <cuda_runtime.h>
#include <cuda_bf16.h>
#include <math.h>
#include <stdint.h>

#define BB   2
#define SS   2048
#define EE   1024
#define E3   3072
#define HH   16
#define DH   64
#define MM   (BB*SS)   // 4096

// ---------------------------------------------------------------------------
// Scratch (__device__ globals; no allocs allowed)
// ---------------------------------------------------------------------------
__device__ float g_qkv [MM * E3];
__device__ float g_attn[MM * EE];
__device__ __nv_bfloat16 g_x_hi [MM * EE], g_x_lo [MM * EE];
__device__ __nv_bfloat16 g_wi_hi[E3 * EE], g_wi_lo[E3 * EE];
__device__ __nv_bfloat16 g_wo_hi[EE * EE], g_wo_lo[EE * EE];
__device__ __nv_bfloat16 g_a_hi [MM * EE], g_a_lo [MM * EE];

// ---------------------------------------------------------------------------
// fp32 -> (hi, lo) bf16 split
// ---------------------------------------------------------------------------
__global__ __launch_bounds__(256) void split_kernel(
    const float* __restrict__ in, __nv_bfloat16* __restrict__ hi,
    __nv_bfloat16* __restrict__ lo, int n4)
{
    int i = blockIdx.x * blockDim.x + threadIdx.x;
    if (i >= n4) return;
    float4 v = ((const float4*)in)[i];
    __nv_bfloat16 hx = __float2bfloat16(v.x);
    __nv_bfloat16 hy = __float2bfloat16(v.y);
    __nv_bfloat16 hz = __float2bfloat16(v.z);
    __nv_bfloat16 hw = __float2bfloat16(v.w);
    __nv_bfloat16 lx = __float2bfloat16(v.x - __bfloat162float(hx));
    __nv_bfloat16 ly = __float2bfloat16(v.y - __bfloat162float(hy));
    __nv_bfloat16 lz = __float2bfloat16(v.z - __bfloat162float(hz));
    __nv_bfloat16 lw = __float2bfloat16(v.w - __bfloat162float(hw));
    __nv_bfloat162* h2 = (__nv_bfloat162*)hi;
    __nv_bfloat162* l2 = (__nv_bfloat162*)lo;
    h2[2*i]   = __nv_bfloat162(hx, hy);
    h2[2*i+1] = __nv_bfloat162(hz, hw);
    l2[2*i]   = __nv_bfloat162(lx, ly);
    l2[2*i+1] = __nv_bfloat162(lz, lw);
}

// ---------------------------------------------------------------------------
// mma.sync m16n8k16 bf16 helper (portable HMMA path; no sm_103a-only PTX)
// ---------------------------------------------------------------------------
__device__ __forceinline__ void mma16816(float* d, const uint32_t* a, const uint32_t* b) {
    asm volatile(
        "mma.sync.aligned.m16n8k16.row.col.f32.bf16.bf16.f32 "
        "{%0,%1,%2,%3}, {%4,%5,%6,%7}, {%8,%9}, {%0,%1,%2,%3};"
        : "+f"(d[0]), "+f"(d[1]), "+f"(d[2]), "+f"(d[3])
        : "r"(a[0]), "r"(a[1]), "r"(a[2]), "r"(a[3]), "r"(b[0]), "r"(b[1]));
}

// ---------------------------------------------------------------------------
// Split-bf16 tensor-core GEMM: C[M,N] = A[M,K] @ W[N,K]^T + bias
// BM=BN=128, BK=32, 256 thr (8 warps as 2m x 4n), warp tile 64x32.
// 3 accumulation passes: Ah*Bh + Ah*Bl + Al*Bh.
// Smem rows padded to 40 bf16 -> conflict-free 32-bit fragment LDS.
// ---------------------------------------------------------------------------
#define SPAD 40

__global__ __launch_bounds__(256) void gemm_mma(
    const __nv_bfloat16* __restrict__ Ahi, const __nv_bfloat16* __restrict__ Alo,
    const __nv_bfloat16* __restrict__ Bhi, const __nv_bfloat16* __restrict__ Blo,
    const float* __restrict__ bias, float* __restrict__ C, int N, int K)
{
    __shared__ __nv_bfloat16 sAh[128][SPAD], sAl[128][SPAD];
    __shared__ __nv_bfloat16 sBh[128][SPAD], sBl[128][SPAD];

    const int tid  = threadIdx.x;
    const int wid  = tid >> 5, lane = tid & 31;
    const int wm   = wid & 1, wn = wid >> 1;        // 2 x 4 warp grid
    const int g    = lane >> 2, ti = lane & 3;      // fragment row group / quad idx
    const int m0   = blockIdx.y * 128, n0 = blockIdx.x * 128;

    float acc[4][4][4] = {};                        // [mfrag][nfrag][4]

    const int nchunk = K >> 5;
    for (int kc = 0; kc < nchunk; kc++) {
        const int kb = kc * 32;
        #pragma unroll
        for (int i = 0; i < 2; i++) {
            int idx = tid + i * 256;                // 0..511
            int row = idx >> 2;
            int kq  = (idx & 3) * 8;
            size_t gA = (size_t)(m0 + row) * K + kb + kq;
            size_t gB = (size_t)(n0 + row) * K + kb + kq;
            *(uint4*)&sAh[row][kq] = *(const uint4*)(Ahi + gA);
            *(uint4*)&sAl[row][kq] = *(const uint4*)(Alo + gA);
            *(uint4*)&sBh[row][kq] = *(const uint4*)(Bhi + gB);
            *(uint4*)&sBl[row][kq] = *(const uint4*)(Blo + gB);
        }
        __syncthreads();

        #pragma unroll
        for (int ks = 0; ks < 2; ks++) {
            const int k16 = ks * 16;
            uint32_t ah[4][4], al[4][4], bh[4][2], bl[4][2];
            #pragma unroll
            for (int mf = 0; mf < 4; mf++) {
                int r = wm * 64 + mf * 16;
                ah[mf][0] = *(const uint32_t*)&sAh[r + g    ][k16 + ti * 2];
                ah[mf][1] = *(const uint32_t*)&sAh[r + g + 8][k16 + ti * 2];
                ah[mf][2] = *(const uint32_t*)&sAh[r + g    ][k16 + ti * 2 + 8];
                ah[mf][3] = *(const uint32_t*)&sAh[r + g + 8][k16 + ti * 2 + 8];
                al[mf][0] = *(const uint32_t*)&sAl[r + g    ][k16 + ti * 2];
                al[mf][1] = *(const uint32_t*)&sAl[r + g + 8][k16 + ti * 2];
                al[mf][2] = *(const uint32_t*)&sAl[r + g    ][k16 + ti * 2 + 8];
                al[mf][3] = *(const uint32_t*)&sAl[r + g + 8][k16 + ti * 2 + 8];
            }
            #pragma unroll
            for (int nf = 0; nf < 4; nf++) {
                int r = wn * 32 + nf * 8 + g;
                bh[nf][0] = *(const uint32_t*)&sBh[r][k16 + ti * 2];
                bh[nf][1] = *(const uint32_t*)&sBh[r][k16 + ti * 2 + 8];
                bl[nf][0] = *(const uint32_t*)&sBl[r][k16 + ti * 2];
                bl[nf][1] = *(const uint32_t*)&sBl[r][k16 + ti * 2 + 8];
            }
            #pragma unroll
            for (int mf = 0; mf < 4; mf++)
                #pragma unroll
                for (int nf = 0; nf < 4; nf++) {
                    mma16816(acc[mf][nf], ah[mf], bh[nf]);
                    mma16816(acc[mf][nf], ah[mf], bl[nf]);
                    mma16816(acc[mf][nf], al[mf], bh[nf]);
                }
        }
        __syncthreads();
    }

    // epilogue
    #pragma unroll
    for (int mf = 0; mf < 4; mf++) {
        int r0 = m0 + wm * 64 + mf * 16 + g;
        #pragma unroll
        for (int nf = 0; nf < 4; nf++) {
            int col = n0 + wn * 32 + nf * 8 + ti * 2;
            float2 bv = *(const float2*)(bias + col);
            float2 o0, o1;
            o0.x = acc[mf][nf][0] + bv.x; o0.y = acc[mf][nf][1] + bv.y;
            o1.x = acc[mf][nf][2] + bv.x; o1.y = acc[mf][nf][3] + bv.y;
            *(float2*)(C + (size_t)r0 * N + col)       = o0;
            *(float2*)(C + (size_t)(r0 + 8) * N + col) = o1;
        }
    }
}

// ---------------------------------------------------------------------------
// Flash attention (fp32, online softmax) — unchanged (FFMA ceiling; next target)
// ---------------------------------------------------------------------------
__global__ __launch_bounds__(256) void attn_kernel(float* __restrict__ out)
{
    __shared__ float Qs[64][64];
    __shared__ float Ks[64][64];
    __shared__ float Vs[64][64];

    const int tid = threadIdx.x;
    const int tx = tid & 15;
    const int ty = tid >> 4;
    const int qt = blockIdx.x;
    const int h  = blockIdx.y;
    const int b  = blockIdx.z;

    const float* qkv = g_qkv;
    const size_t rowstride = E3;
    const size_t qbase = (size_t)(b * SS + qt * 64) * rowstride + h * DH;

    #pragma unroll
    for (int it = 0; it < 4; it++) {
        int f = it * 256 + tid;
        int r  = f & 63;
        int c4 = (f >> 6) * 4;
        float4 v = *(const float4*)&qkv[qbase + (size_t)r * rowstride + c4];
        Qs[c4 + 0][r] = v.x; Qs[c4 + 1][r] = v.y;
        Qs[c4 + 2][r] = v.z; Qs[c4 + 3][r] = v.w;
    }

    float m[4], l[4], accO[4][4] = {};
    #pragma unroll
    for (int i = 0; i < 4; i++) { m[i] = -1e30f; l[i] = 0.0f; }

    const float scale = 0.125f;

    for (int kt = 0; kt < SS / 64; kt++) {
        __syncthreads();

        const size_t kbase = (size_t)(b * SS + kt * 64) * rowstride + EE  + h * DH;
        const size_t vbase = (size_t)(b * SS + kt * 64) * rowstride + 2 * EE + h * DH;
        #pragma unroll
        for (int it = 0; it < 4; it++) {
            int f = it * 256 + tid;
            int r  = f & 63;
            int c4 = (f >> 6) * 4;
            float4 kv = *(const float4*)&qkv[kbase + (size_t)r * rowstride + c4];
            Ks[c4 + 0][r] = kv.x; Ks[c4 + 1][r] = kv.y;
            Ks[c4 + 2][r] = kv.z; Ks[c4 + 3][r] = kv.w;
            int vr  = f >> 4;
            int vc4 = (f & 15) * 4;
            float4 vv = *(const float4*)&qkv[vbase + (size_t)vr * rowstride + vc4];
            *(float4*)&Vs[vr][vc4] = vv;
        }
        __syncthreads();

        float sacc[4][4] = {};
        #pragma unroll 16
        for (int kk = 0; kk < 64; kk++) {
            float4 a = *(const float4*)&Qs[kk][ty * 4];
            float4 c = *(const float4*)&Ks[kk][tx * 4];
            sacc[0][0] += a.x * c.x; sacc[0][1] += a.x * c.y;
            sacc[0][2] += a.x * c.z; sacc[0][3] += a.x * c.w;
            sacc[1][0] += a.y * c.x; sacc[1][1] += a.y * c.y;
            sacc[1][2] += a.y * c.z; sacc[1][3] += a.y * c.w;
            sacc[2][0] += a.z * c.x; sacc[2][1] += a.z * c.y;
            sacc[2][2] += a.z * c.z; sacc[2][3] += a.z * c.w;
            sacc[3][0] += a.w * c.x; sacc[3][1] += a.w * c.y;
            sacc[3][2] += a.w * c.z; sacc[3][3] += a.w * c.w;
        }

        float p[4][4];
        #pragma unroll
        for (int i = 0; i < 4; i++) {
            float s0 = sacc[i][0] * scale, s1 = sacc[i][1] * scale;
            float s2 = sacc[i][2] * scale, s3 = sacc[i][3] * scale;
            float mx = fmaxf(fmaxf(s0, s1), fmaxf(s2, s3));
            #pragma unroll
            for (int off = 8; off >= 1; off >>= 1)
                mx = fmaxf(mx, __shfl_xor_sync(0xffffffffu, mx, off));
            float mnew = fmaxf(m[i], mx);
            float corr = __expf(m[i] - mnew);
            p[i][0] = __expf(s0 - mnew);
            p[i][1] = __expf(s1 - mnew);
            p[i][2] = __expf(s2 - mnew);
            p[i][3] = __expf(s3 - mnew);
            float rs = p[i][0] + p[i][1] + p[i][2] + p[i][3];
            #pragma unroll
            for (int off = 8; off >= 1; off >>= 1)
                rs += __shfl_xor_sync(0xffffffffu, rs, off);
            l[i] = l[i] * corr + rs;
            m[i] = mnew;
            accO[i][0] *= corr; accO[i][1] *= corr;
            accO[i][2] *= corr; accO[i][3] *= corr;
        }

        __syncthreads();

        #pragma unroll
        for (int i = 0; i < 4; i++) {
            float4 pv = make_float4(p[i][0], p[i][1], p[i][2], p[i][3]);
            *(float4*)&Ks[ty * 4 + i][tx * 4] = pv;
        }
        __syncthreads();

        #pragma unroll 16
        for (int kk = 0; kk < 64; kk++) {
            float a0 = Ks[ty * 4 + 0][kk];
            float a1 = Ks[ty * 4 + 1][kk];
            float a2 = Ks[ty * 4 + 2][kk];
            float a3 = Ks[ty * 4 + 3][kk];
            float4 v = *(const float4*)&Vs[kk][tx * 4];
            accO[0][0] += a0 * v.x; accO[0][1] += a0 * v.y;
            accO[0][2] += a0 * v.z; accO[0][3] += a0 * v.w;
            accO[1][0] += a1 * v.x; accO[1][1] += a1 * v.y;
            accO[1][2] += a1 * v.z; accO[1][3] += a1 * v.w;
            accO[2][0] += a2 * v.x; accO[2][1] += a2 * v.y;
            accO[2][2] += a2 * v.z; accO[2][3] += a2 * v.w;
            accO[3][0] += a3 * v.x; accO[3][1] += a3 * v.y;
            accO[3][2] += a3 * v.z; accO[3][3] += a3 * v.w;
        }
    }

    #pragma unroll
    for (int i = 0; i < 4; i++) {
        float inv = 1.0f / l[i];
        float4 o;
        o.x = accO[i][0] * inv; o.y = accO[i][1] * inv;
        o.z = accO[i][2] * inv; o.w = accO[i][3] * inv;
        size_t row = (size_t)(b * SS + qt * 64 + ty * 4 + i);
        *(float4*)&out[row * EE + h * DH + tx * 4] = o;
    }
}

// ---------------------------------------------------------------------------
extern "C" void kernel_launch(void* const* d_in, const int* in_sizes, int n_in,
                              void* d_out, int out_size)
{
    const float* x     = (const float*)d_in[0];
    const float* w_in  = (const float*)d_in[1];
    const float* b_in  = (const float*)d_in[2];
    const float* w_out = (const float*)d_in[3];
    const float* b_out = (const float*)d_in[4];
    float* out = (float*)d_out;

    float *qkv, *attn;
    __nv_bfloat16 *xh, *xl, *wih, *wil, *woh, *wol, *ah, *al;
    cudaGetSymbolAddress((void**)&qkv,  g_qkv);
    cudaGetSymbolAddress((void**)&attn, g_attn);
    cudaGetSymbolAddress((void**)&xh,  g_x_hi);  cudaGetSymbolAddress((void**)&xl,  g_x_lo);
    cudaGetSymbolAddress((void**)&wih, g_wi_hi); cudaGetSymbolAddress((void**)&wil, g_wi_lo);
    cudaGetSymbolAddress((void**)&woh, g_wo_hi); cudaGetSymbolAddress((void**)&wol, g_wo_lo);
    cudaGetSymbolAddress((void**)&ah,  g_a_hi);  cudaGetSymbolAddress((void**)&al,  g_a_lo);

    // 1) split inputs to hi/lo bf16
    split_kernel<<<(MM * EE / 4 + 255) / 256, 256>>>(x,     xh,  xl,  MM * EE / 4);
    split_kernel<<<(E3 * EE / 4 + 255) / 256, 256>>>(w_in,  wih, wil, E3 * EE / 4);
    split_kernel<<<(EE * EE / 4 + 255) / 256, 256>>>(w_out, woh, wol, EE * EE / 4);

    // 2) QKV projection (HMMA): [4096,3072] = x @ w_in^T + b_in
    gemm_mma<<<dim3(E3 / 128, MM / 128), 256>>>(xh, xl, wih, wil, b_in, qkv, E3, EE);

    // 3) attention
    attn_kernel<<<dim3(SS / 64, HH, BB), 256>>>(attn);

    // 4) split attention output, 5) out projection (HMMA)
    split_kernel<<<(MM * EE / 4 + 255) / 256, 256>>>(attn, ah, al, MM * EE / 4);
    gemm_mma<<<dim3(EE / 128, MM / 128), 256>>>(ah, al, woh, wol, b_out, out, EE, EE);
}

// round 5
// speedup vs baseline: 2.5216x; 1.7861x over previous
#include <cuda_runtime.h>
#include <cuda_bf16.h>
#include <math.h>
#include <stdint.h>

#define BB   2
#define SS   2048
#define EE   1024
#define E3   3072
#define HH   16
#define DH   64
#define MM   (BB*SS)   // 4096

// ---------------------------------------------------------------------------
// Scratch (__device__ globals; no allocs allowed)
// ---------------------------------------------------------------------------
__device__ float g_qkv [MM * E3];
__device__ float g_attn[MM * EE];
__device__ __nv_bfloat16 g_x_hi [MM * EE], g_x_lo [MM * EE];
__device__ __nv_bfloat16 g_wi_hi[E3 * EE], g_wi_lo[E3 * EE];
__device__ __nv_bfloat16 g_wo_hi[EE * EE], g_wo_lo[EE * EE];
__device__ __nv_bfloat16 g_a_hi [MM * EE], g_a_lo [MM * EE];
__device__ __nv_bfloat16 g_qkv_hi[MM * E3], g_qkv_lo[MM * E3];

// ---------------------------------------------------------------------------
// helpers
// ---------------------------------------------------------------------------
__device__ __forceinline__ void mma16816(float* d, const uint32_t* a, const uint32_t* b) {
    asm volatile(
        "mma.sync.aligned.m16n8k16.row.col.f32.bf16.bf16.f32 "
        "{%0,%1,%2,%3}, {%4,%5,%6,%7}, {%8,%9}, {%0,%1,%2,%3};"
        : "+f"(d[0]), "+f"(d[1]), "+f"(d[2]), "+f"(d[3])
        : "r"(a[0]), "r"(a[1]), "r"(a[2]), "r"(a[3]), "r"(b[0]), "r"(b[1]));
}
__device__ __forceinline__ void ldsm4t(uint32_t* r, uint32_t saddr) {
    asm volatile("ldmatrix.sync.aligned.m8n8.x4.trans.shared.b16 {%0,%1,%2,%3}, [%4];"
        : "=r"(r[0]), "=r"(r[1]), "=r"(r[2]), "=r"(r[3]) : "r"(saddr));
}
__device__ __forceinline__ uint32_t s2u(const void* p) {
    return (uint32_t)__cvta_generic_to_shared(p);
}
__device__ __forceinline__ uint32_t pack2(__nv_bfloat16 a, __nv_bfloat16 b) {
    __nv_bfloat162 t(a, b);
    return *(uint32_t*)&t;
}

// ---------------------------------------------------------------------------
// fp32 -> (hi, lo) bf16 split
// ---------------------------------------------------------------------------
__global__ __launch_bounds__(256) void split_kernel(
    const float* __restrict__ in, __nv_bfloat16* __restrict__ hi,
    __nv_bfloat16* __restrict__ lo, int n4)
{
    int i = blockIdx.x * blockDim.x + threadIdx.x;
    if (i >= n4) return;
    float4 v = ((const float4*)in)[i];
    __nv_bfloat16 hx = __float2bfloat16(v.x);
    __nv_bfloat16 hy = __float2bfloat16(v.y);
    __nv_bfloat16 hz = __float2bfloat16(v.z);
    __nv_bfloat16 hw = __float2bfloat16(v.w);
    __nv_bfloat16 lx = __float2bfloat16(v.x - __bfloat162float(hx));
    __nv_bfloat16 ly = __float2bfloat16(v.y - __bfloat162float(hy));
    __nv_bfloat16 lz = __float2bfloat16(v.z - __bfloat162float(hz));
    __nv_bfloat16 lw = __float2bfloat16(v.w - __bfloat162float(hw));
    __nv_bfloat162* h2 = (__nv_bfloat162*)hi;
    __nv_bfloat162* l2 = (__nv_bfloat162*)lo;
    h2[2*i]   = __nv_bfloat162(hx, hy);
    h2[2*i+1] = __nv_bfloat162(hz, hw);
    l2[2*i]   = __nv_bfloat162(lx, ly);
    l2[2*i+1] = __nv_bfloat162(lz, lw);
}

// ---------------------------------------------------------------------------
// Split-bf16 HMMA GEMM: C[M,N] = A[M,K] @ W[N,K]^T + bias
// BM=BN=128, BK=32, 256 thr (2m x 4n warps), warp tile 64x32.
// A-frags streamed per-mf to cut registers; 2 CTAs/SM forced.
// ---------------------------------------------------------------------------
#define SPAD 40

__global__ __launch_bounds__(256, 2) void gemm_mma(
    const __nv_bfloat16* __restrict__ Ahi, const __nv_bfloat16* __restrict__ Alo,
    const __nv_bfloat16* __restrict__ Bhi, const __nv_bfloat16* __restrict__ Blo,
    const float* __restrict__ bias, float* __restrict__ C, int N, int K)
{
    __shared__ __align__(16) __nv_bfloat16 sAh[128][SPAD], sAl[128][SPAD];
    __shared__ __align__(16) __nv_bfloat16 sBh[128][SPAD], sBl[128][SPAD];

    const int tid  = threadIdx.x;
    const int wid  = tid >> 5, lane = tid & 31;
    const int wm   = wid & 1, wn = wid >> 1;
    const int g    = lane >> 2, ti = lane & 3;
    const int m0   = blockIdx.y * 128, n0 = blockIdx.x * 128;

    float acc[4][4][4] = {};

    const int nchunk = K >> 5;
    for (int kc = 0; kc < nchunk; kc++) {
        const int kb = kc * 32;
        #pragma unroll
        for (int i = 0; i < 2; i++) {
            int idx = tid + i * 256;
            int row = idx >> 2;
            int kq  = (idx & 3) * 8;
            size_t gA = (size_t)(m0 + row) * K + kb + kq;
            size_t gB = (size_t)(n0 + row) * K + kb + kq;
            *(uint4*)&sAh[row][kq] = *(const uint4*)(Ahi + gA);
            *(uint4*)&sAl[row][kq] = *(const uint4*)(Alo + gA);
            *(uint4*)&sBh[row][kq] = *(const uint4*)(Bhi + gB);
            *(uint4*)&sBl[row][kq] = *(const uint4*)(Blo + gB);
        }
        __syncthreads();

        #pragma unroll
        for (int ks = 0; ks < 2; ks++) {
            const int k16 = ks * 16;
            uint32_t bh[4][2], bl[4][2];
            #pragma unroll
            for (int nf = 0; nf < 4; nf++) {
                int r = wn * 32 + nf * 8 + g;
                bh[nf][0] = *(const uint32_t*)&sBh[r][k16 + ti * 2];
                bh[nf][1] = *(const uint32_t*)&sBh[r][k16 + ti * 2 + 8];
                bl[nf][0] = *(const uint32_t*)&sBl[r][k16 + ti * 2];
                bl[nf][1] = *(const uint32_t*)&sBl[r][k16 + ti * 2 + 8];
            }
            #pragma unroll
            for (int mf = 0; mf < 4; mf++) {
                int r = wm * 64 + mf * 16;
                uint32_t ah[4], al[4];
                ah[0] = *(const uint32_t*)&sAh[r + g    ][k16 + ti * 2];
                ah[1] = *(const uint32_t*)&sAh[r + g + 8][k16 + ti * 2];
                ah[2] = *(const uint32_t*)&sAh[r + g    ][k16 + ti * 2 + 8];
                ah[3] = *(const uint32_t*)&sAh[r + g + 8][k16 + ti * 2 + 8];
                al[0] = *(const uint32_t*)&sAl[r + g    ][k16 + ti * 2];
                al[1] = *(const uint32_t*)&sAl[r + g + 8][k16 + ti * 2];
                al[2] = *(const uint32_t*)&sAl[r + g    ][k16 + ti * 2 + 8];
                al[3] = *(const uint32_t*)&sAl[r + g + 8][k16 + ti * 2 + 8];
                #pragma unroll
                for (int nf = 0; nf < 4; nf++) {
                    mma16816(acc[mf][nf], ah, bh[nf]);
                    mma16816(acc[mf][nf], ah, bl[nf]);
                    mma16816(acc[mf][nf], al, bh[nf]);
                }
            }
        }
        __syncthreads();
    }

    #pragma unroll
    for (int mf = 0; mf < 4; mf++) {
        int r0 = m0 + wm * 64 + mf * 16 + g;
        #pragma unroll
        for (int nf = 0; nf < 4; nf++) {
            int col = n0 + wn * 32 + nf * 8 + ti * 2;
            float2 bv = *(const float2*)(bias + col);
            float2 o0, o1;
            o0.x = acc[mf][nf][0] + bv.x; o0.y = acc[mf][nf][1] + bv.y;
            o1.x = acc[mf][nf][2] + bv.x; o1.y = acc[mf][nf][3] + bv.y;
            *(float2*)(C + (size_t)r0 * N + col)       = o0;
            *(float2*)(C + (size_t)(r0 + 8) * N + col) = o1;
        }
    }
}

// ---------------------------------------------------------------------------
// Tensor-core flash attention, split-bf16, P in registers (FA2 style).
// Block = (qt 64 rows, h, b); 128 threads = 4 warps x 16 q-rows.
// ---------------------------------------------------------------------------
__global__ __launch_bounds__(128) void attn_mma(
    const __nv_bfloat16* __restrict__ qg_h, const __nv_bfloat16* __restrict__ qg_l,
    float* __restrict__ out)
{
    __shared__ __align__(16) __nv_bfloat16 sKh[64][72], sKl[64][72];
    __shared__ __align__(16) __nv_bfloat16 sVh[64][72], sVl[64][72];

    const int tid = threadIdx.x;
    const int wid = tid >> 5, lane = tid & 31;
    const int g = lane >> 2, ti = lane & 3;
    const int qt = blockIdx.x, h = blockIdx.y, b = blockIdx.z;
    const int h64 = h * DH;
    const size_t qrow0 = (size_t)(b * SS + qt * 64);

    // stage Q tile (hi/lo) into the K buffers, extract A-frags, keep in regs
    #pragma unroll
    for (int i = 0; i < 4; i++) {
        int idx = tid + i * 128;
        int row = idx >> 3, c8 = (idx & 7) * 8;
        size_t go = (qrow0 + row) * E3 + h64 + c8;
        *(uint4*)&sKh[row][c8] = *(const uint4*)(qg_h + go);
        *(uint4*)&sKl[row][c8] = *(const uint4*)(qg_l + go);
    }
    __syncthreads();
    uint32_t qh[4][4], ql[4][4];
    #pragma unroll
    for (int ks = 0; ks < 4; ks++) {
        int k16 = ks * 16;
        int r = wid * 16;
        qh[ks][0] = *(const uint32_t*)&sKh[r + g    ][k16 + 2 * ti];
        qh[ks][1] = *(const uint32_t*)&sKh[r + g + 8][k16 + 2 * ti];
        qh[ks][2] = *(const uint32_t*)&sKh[r + g    ][k16 + 8 + 2 * ti];
        qh[ks][3] = *(const uint32_t*)&sKh[r + g + 8][k16 + 8 + 2 * ti];
        ql[ks][0] = *(const uint32_t*)&sKl[r + g    ][k16 + 2 * ti];
        ql[ks][1] = *(const uint32_t*)&sKl[r + g + 8][k16 + 2 * ti];
        ql[ks][2] = *(const uint32_t*)&sKl[r + g    ][k16 + 8 + 2 * ti];
        ql[ks][3] = *(const uint32_t*)&sKl[r + g + 8][k16 + 8 + 2 * ti];
    }
    __syncthreads();

    float m0 = -1e30f, m1 = -1e30f, l0 = 0.f, l1 = 0.f;
    float accO[8][4] = {};
    const float scale = 0.125f;   // 1/sqrt(64)

    for (int kt = 0; kt < SS / 64; kt++) {
        const size_t krow0 = (size_t)(b * SS + kt * 64);
        #pragma unroll
        for (int i = 0; i < 4; i++) {
            int idx = tid + i * 128;
            int row = idx >> 3, c8 = (idx & 7) * 8;
            size_t gk = (krow0 + row) * E3 +     EE + h64 + c8;
            size_t gv = (krow0 + row) * E3 + 2 * EE + h64 + c8;
            *(uint4*)&sKh[row][c8] = *(const uint4*)(qg_h + gk);
            *(uint4*)&sKl[row][c8] = *(const uint4*)(qg_l + gk);
            *(uint4*)&sVh[row][c8] = *(const uint4*)(qg_h + gv);
            *(uint4*)&sVl[row][c8] = *(const uint4*)(qg_l + gv);
        }
        __syncthreads();

        // S = Q K^T (3-term split)
        float sacc[8][4] = {};
        #pragma unroll
        for (int ks = 0; ks < 4; ks++) {
            int k16 = ks * 16;
            #pragma unroll
            for (int nf = 0; nf < 8; nf++) {
                int r = nf * 8 + g;
                uint32_t kb[2], klb[2];
                kb[0]  = *(const uint32_t*)&sKh[r][k16 + 2 * ti];
                kb[1]  = *(const uint32_t*)&sKh[r][k16 + 8 + 2 * ti];
                klb[0] = *(const uint32_t*)&sKl[r][k16 + 2 * ti];
                klb[1] = *(const uint32_t*)&sKl[r][k16 + 8 + 2 * ti];
                mma16816(sacc[nf], qh[ks], kb);
                mma16816(sacc[nf], qh[ks], klb);
                mma16816(sacc[nf], ql[ks], kb);
            }
        }

        // online softmax (rows g and g+8; quad lanes share a row)
        float mx0 = -1e30f, mx1 = -1e30f;
        #pragma unroll
        for (int nf = 0; nf < 8; nf++) {
            sacc[nf][0] *= scale; sacc[nf][1] *= scale;
            sacc[nf][2] *= scale; sacc[nf][3] *= scale;
            mx0 = fmaxf(mx0, fmaxf(sacc[nf][0], sacc[nf][1]));
            mx1 = fmaxf(mx1, fmaxf(sacc[nf][2], sacc[nf][3]));
        }
        mx0 = fmaxf(mx0, __shfl_xor_sync(0xffffffffu, mx0, 1));
        mx0 = fmaxf(mx0, __shfl_xor_sync(0xffffffffu, mx0, 2));
        mx1 = fmaxf(mx1, __shfl_xor_sync(0xffffffffu, mx1, 1));
        mx1 = fmaxf(mx1, __shfl_xor_sync(0xffffffffu, mx1, 2));
        float mn0 = fmaxf(m0, mx0), mn1 = fmaxf(m1, mx1);
        float c0 = __expf(m0 - mn0), c1 = __expf(m1 - mn1);
        float rs0 = 0.f, rs1 = 0.f;
        #pragma unroll
        for (int nf = 0; nf < 8; nf++) {
            sacc[nf][0] = __expf(sacc[nf][0] - mn0);
            sacc[nf][1] = __expf(sacc[nf][1] - mn0);
            sacc[nf][2] = __expf(sacc[nf][2] - mn1);
            sacc[nf][3] = __expf(sacc[nf][3] - mn1);
            rs0 += sacc[nf][0] + sacc[nf][1];
            rs1 += sacc[nf][2] + sacc[nf][3];
        }
        rs0 += __shfl_xor_sync(0xffffffffu, rs0, 1);
        rs0 += __shfl_xor_sync(0xffffffffu, rs0, 2);
        rs1 += __shfl_xor_sync(0xffffffffu, rs1, 1);
        rs1 += __shfl_xor_sync(0xffffffffu, rs1, 2);
        l0 = l0 * c0 + rs0; l1 = l1 * c1 + rs1;
        m0 = mn0; m1 = mn1;
        #pragma unroll
        for (int nf = 0; nf < 8; nf++) {
            accO[nf][0] *= c0; accO[nf][1] *= c0;
            accO[nf][2] *= c1; accO[nf][3] *= c1;
        }

        // O += P V  (P hi/lo in registers, V hi/lo via ldmatrix.trans)
        #pragma unroll
        for (int ks2 = 0; ks2 < 4; ks2++) {
            const int f0 = 2 * ks2, f1 = 2 * ks2 + 1;
            __nv_bfloat16 h00 = __float2bfloat16(sacc[f0][0]);
            __nv_bfloat16 h01 = __float2bfloat16(sacc[f0][1]);
            __nv_bfloat16 h02 = __float2bfloat16(sacc[f0][2]);
            __nv_bfloat16 h03 = __float2bfloat16(sacc[f0][3]);
            __nv_bfloat16 h10 = __float2bfloat16(sacc[f1][0]);
            __nv_bfloat16 h11 = __float2bfloat16(sacc[f1][1]);
            __nv_bfloat16 h12 = __float2bfloat16(sacc[f1][2]);
            __nv_bfloat16 h13 = __float2bfloat16(sacc[f1][3]);
            uint32_t pa[4], pl[4];
            pa[0] = pack2(h00, h01); pa[1] = pack2(h02, h03);
            pa[2] = pack2(h10, h11); pa[3] = pack2(h12, h13);
            pl[0] = pack2(__float2bfloat16(sacc[f0][0] - __bfloat162float(h00)),
                          __float2bfloat16(sacc[f0][1] - __bfloat162float(h01)));
            pl[1] = pack2(__float2bfloat16(sacc[f0][2] - __bfloat162float(h02)),
                          __float2bfloat16(sacc[f0][3] - __bfloat162float(h03)));
            pl[2] = pack2(__float2bfloat16(sacc[f1][0] - __bfloat162float(h10)),
                          __float2bfloat16(sacc[f1][1] - __bfloat162float(h11)));
            pl[3] = pack2(__float2bfloat16(sacc[f1][2] - __bfloat162float(h12)),
                          __float2bfloat16(sacc[f1][3] - __bfloat162float(h13)));

            const int k16 = ks2 * 16;
            const int quad = lane >> 3;
            const int vrow = k16 + (lane & 7) + (quad & 1) * 8;
            #pragma unroll
            for (int np = 0; np < 4; np++) {
                const int vcol = np * 16 + (quad >> 1) * 8;
                uint32_t vb[4], vlb[4];
                ldsm4t(vb,  s2u(&sVh[vrow][vcol]));
                ldsm4t(vlb, s2u(&sVl[vrow][vcol]));
                mma16816(accO[np*2],     pa, vb);
                mma16816(accO[np*2],     pa, vlb);
                mma16816(accO[np*2],     pl, vb);
                mma16816(accO[np*2 + 1], pa, vb + 2);
                mma16816(accO[np*2 + 1], pa, vlb + 2);
                mma16816(accO[np*2 + 1], pl, vb + 2);
            }
        }
        __syncthreads();
    }

    // epilogue
    const float inv0 = 1.0f / l0, inv1 = 1.0f / l1;
    const size_t r0 = qrow0 + wid * 16 + g;
    #pragma unroll
    for (int nf = 0; nf < 8; nf++) {
        int col = h64 + nf * 8 + 2 * ti;
        float2 o0, o1;
        o0.x = accO[nf][0] * inv0; o0.y = accO[nf][1] * inv0;
        o1.x = accO[nf][2] * inv1; o1.y = accO[nf][3] * inv1;
        *(float2*)(out + r0 * EE + col)       = o0;
        *(float2*)(out + (r0 + 8) * EE + col) = o1;
    }
}

// ---------------------------------------------------------------------------
extern "C" void kernel_launch(void* const* d_in, const int* in_sizes, int n_in,
                              void* d_out, int out_size)
{
    const float* x     = (const float*)d_in[0];
    const float* w_in  = (const float*)d_in[1];
    const float* b_in  = (const float*)d_in[2];
    const float* w_out = (const float*)d_in[3];
    const float* b_out = (const float*)d_in[4];
    float* out = (float*)d_out;

    float *qkv, *attn;
    __nv_bfloat16 *xh, *xl, *wih, *wil, *woh, *wol, *ah, *al, *qkh, *qkl;
    cudaGetSymbolAddress((void**)&qkv,  g_qkv);
    cudaGetSymbolAddress((void**)&attn, g_attn);
    cudaGetSymbolAddress((void**)&xh,  g_x_hi);   cudaGetSymbolAddress((void**)&xl,  g_x_lo);
    cudaGetSymbolAddress((void**)&wih, g_wi_hi);  cudaGetSymbolAddress((void**)&wil, g_wi_lo);
    cudaGetSymbolAddress((void**)&woh, g_wo_hi);  cudaGetSymbolAddress((void**)&wol, g_wo_lo);
    cudaGetSymbolAddress((void**)&ah,  g_a_hi);   cudaGetSymbolAddress((void**)&al,  g_a_lo);
    cudaGetSymbolAddress((void**)&qkh, g_qkv_hi); cudaGetSymbolAddress((void**)&qkl, g_qkv_lo);

    // 1) split inputs
    split_kernel<<<(MM * EE / 4 + 255) / 256, 256>>>(x,     xh,  xl,  MM * EE / 4);
    split_kernel<<<(E3 * EE / 4 + 255) / 256, 256>>>(w_in,  wih, wil, E3 * EE / 4);
    split_kernel<<<(EE * EE / 4 + 255) / 256, 256>>>(w_out, woh, wol, EE * EE / 4);

    // 2) QKV projection
    gemm_mma<<<dim3(E3 / 128, MM / 128), 256>>>(xh, xl, wih, wil, b_in, qkv, E3, EE);

    // 3) split qkv, tensor-core attention
    split_kernel<<<(MM * E3 / 4 + 255) / 256, 256>>>(qkv, qkh, qkl, MM * E3 / 4);
    attn_mma<<<dim3(SS / 64, HH, BB), 128>>>(qkh, qkl, attn);

    // 4) split attention output, out projection
    split_kernel<<<(MM * EE / 4 + 255) / 256, 256>>>(attn, ah, al, MM * EE / 4);
    gemm_mma<<<dim3(EE / 128, MM / 128), 256>>>(ah, al, woh, wol, b_out, out, EE, EE);
}

// round 6
// speedup vs baseline: 3.0545x; 1.2113x over previous
#include <cuda_runtime.h>
#include <cuda_bf16.h>
#include <math.h>
#include <stdint.h>

#define BB   2
#define SS   2048
#define EE   1024
#define E3   3072
#define HH   16
#define DH   64
#define MM   (BB*SS)   // 4096

// ---------------------------------------------------------------------------
// Scratch (__device__ globals; no allocs allowed)
// ---------------------------------------------------------------------------
__device__ __nv_bfloat16 g_x_hi [MM * EE], g_x_lo [MM * EE];
__device__ __nv_bfloat16 g_wi_hi[E3 * EE], g_wi_lo[E3 * EE];
__device__ __nv_bfloat16 g_wo_hi[EE * EE], g_wo_lo[EE * EE];
__device__ __nv_bfloat16 g_a_hi [MM * EE], g_a_lo [MM * EE];
__device__ __nv_bfloat16 g_qkv_hi[MM * E3], g_qkv_lo[MM * E3];

// ---------------------------------------------------------------------------
// helpers
// ---------------------------------------------------------------------------
__device__ __forceinline__ void mma16816(float* d, const uint32_t* a, const uint32_t* b) {
    asm volatile(
        "mma.sync.aligned.m16n8k16.row.col.f32.bf16.bf16.f32 "
        "{%0,%1,%2,%3}, {%4,%5,%6,%7}, {%8,%9}, {%0,%1,%2,%3};"
        : "+f"(d[0]), "+f"(d[1]), "+f"(d[2]), "+f"(d[3])
        : "r"(a[0]), "r"(a[1]), "r"(a[2]), "r"(a[3]), "r"(b[0]), "r"(b[1]));
}
__device__ __forceinline__ void ldsm4t(uint32_t* r, uint32_t saddr) {
    asm volatile("ldmatrix.sync.aligned.m8n8.x4.trans.shared.b16 {%0,%1,%2,%3}, [%4];"
        : "=r"(r[0]), "=r"(r[1]), "=r"(r[2]), "=r"(r[3]) : "r"(saddr));
}
__device__ __forceinline__ uint32_t s2u(const void* p) {
    return (uint32_t)__cvta_generic_to_shared(p);
}
__device__ __forceinline__ uint32_t pack2(__nv_bfloat16 a, __nv_bfloat16 b) {
    __nv_bfloat162 t(a, b);
    return *(uint32_t*)&t;
}
__device__ __forceinline__ void cpa16(uint32_t s, const void* g) {
    asm volatile("cp.async.cg.shared.global [%0], [%1], 16;" :: "r"(s), "l"(g));
}
#define CPA_COMMIT()  asm volatile("cp.async.commit_group;" ::: "memory")
#define CPA_WAIT(n)   asm volatile("cp.async.wait_group %0;" :: "n"(n) : "memory")

// split fp32 -> (hi,lo) bf16 pair
__device__ __forceinline__ void split1(float v, __nv_bfloat16& h, __nv_bfloat16& l) {
    h = __float2bfloat16(v);
    l = __float2bfloat16(v - __bfloat162float(h));
}

// ---------------------------------------------------------------------------
// fp32 -> (hi, lo) bf16 split (inputs only)
// ---------------------------------------------------------------------------
__global__ __launch_bounds__(256) void split_kernel(
    const float* __restrict__ in, __nv_bfloat16* __restrict__ hi,
    __nv_bfloat16* __restrict__ lo, int n4)
{
    int i = blockIdx.x * blockDim.x + threadIdx.x;
    if (i >= n4) return;
    float4 v = ((const float4*)in)[i];
    __nv_bfloat16 hx, hy, hz, hw, lx, ly, lz, lw;
    split1(v.x, hx, lx); split1(v.y, hy, ly);
    split1(v.z, hz, lz); split1(v.w, hw, lw);
    __nv_bfloat162* h2 = (__nv_bfloat162*)hi;
    __nv_bfloat162* l2 = (__nv_bfloat162*)lo;
    h2[2*i]   = __nv_bfloat162(hx, hy);
    h2[2*i+1] = __nv_bfloat162(hz, hw);
    l2[2*i]   = __nv_bfloat162(lx, ly);
    l2[2*i+1] = __nv_bfloat162(lz, lw);
}

// ---------------------------------------------------------------------------
// Split-bf16 HMMA GEMM, cp.async 2-stage pipeline.
// BM=BN=128, BK=32, 256 thr (2m x 4n warps), warp tile 64x32.
// SPLIT=true: write bf16 hi/lo outputs; else fp32 C.
// ---------------------------------------------------------------------------
#define SPAD 40
#define GARR (128 * SPAD)                 // elems per array (5120)
#define GSTG (4 * GARR)                   // elems per stage
#define GEMM_SMEM (2 * GSTG * 2)          // bytes = 81920

template<bool SPLIT>
__global__ __launch_bounds__(256, 2) void gemm_mma(
    const __nv_bfloat16* __restrict__ Ahi, const __nv_bfloat16* __restrict__ Alo,
    const __nv_bfloat16* __restrict__ Bhi, const __nv_bfloat16* __restrict__ Blo,
    const float* __restrict__ bias, float* __restrict__ C,
    __nv_bfloat16* __restrict__ Ch, __nv_bfloat16* __restrict__ Cl,
    int N, int K)
{
    extern __shared__ __align__(16) __nv_bfloat16 dsm[];

    const int tid  = threadIdx.x;
    const int wid  = tid >> 5, lane = tid & 31;
    const int wm   = wid & 1, wn = wid >> 1;
    const int g    = lane >> 2, ti = lane & 3;
    const int m0   = blockIdx.y * 128, n0 = blockIdx.x * 128;

    const int lrow = tid >> 2;            // 0..63 (x2 halves)
    const int lkq  = (tid & 3) * 8;

    auto issue = [&](int kc, int s) {
        __nv_bfloat16* base = dsm + s * GSTG;
        const int kb = kc * 32;
        #pragma unroll
        for (int i = 0; i < 2; i++) {
            int row = lrow + i * 64;
            int off = row * SPAD + lkq;
            size_t gA = (size_t)(m0 + row) * K + kb + lkq;
            size_t gB = (size_t)(n0 + row) * K + kb + lkq;
            cpa16(s2u(base + off),            Ahi + gA);
            cpa16(s2u(base + GARR + off),     Alo + gA);
            cpa16(s2u(base + 2 * GARR + off), Bhi + gB);
            cpa16(s2u(base + 3 * GARR + off), Blo + gB);
        }
    };

    float acc[4][4][4] = {};
    const int nchunk = K >> 5;

    issue(0, 0); CPA_COMMIT();

    for (int kc = 0; kc < nchunk; kc++) {
        if (kc + 1 < nchunk) { issue(kc + 1, (kc + 1) & 1); CPA_COMMIT(); CPA_WAIT(1); }
        else                 { CPA_WAIT(0); }
        __syncthreads();

        const __nv_bfloat16* sAh = dsm + (kc & 1) * GSTG;
        const __nv_bfloat16* sAl = sAh + GARR;
        const __nv_bfloat16* sBh = sAh + 2 * GARR;
        const __nv_bfloat16* sBl = sAh + 3 * GARR;

        #pragma unroll
        for (int ks = 0; ks < 2; ks++) {
            const int k16 = ks * 16;
            uint32_t bh[4][2], bl[4][2];
            #pragma unroll
            for (int nf = 0; nf < 4; nf++) {
                int r = wn * 32 + nf * 8 + g;
                bh[nf][0] = *(const uint32_t*)&sBh[r * SPAD + k16 + ti * 2];
                bh[nf][1] = *(const uint32_t*)&sBh[r * SPAD + k16 + ti * 2 + 8];
                bl[nf][0] = *(const uint32_t*)&sBl[r * SPAD + k16 + ti * 2];
                bl[nf][1] = *(const uint32_t*)&sBl[r * SPAD + k16 + ti * 2 + 8];
            }
            #pragma unroll
            for (int mf = 0; mf < 4; mf++) {
                int r = wm * 64 + mf * 16;
                uint32_t ah[4], al[4];
                ah[0] = *(const uint32_t*)&sAh[(r + g    ) * SPAD + k16 + ti * 2];
                ah[1] = *(const uint32_t*)&sAh[(r + g + 8) * SPAD + k16 + ti * 2];
                ah[2] = *(const uint32_t*)&sAh[(r + g    ) * SPAD + k16 + ti * 2 + 8];
                ah[3] = *(const uint32_t*)&sAh[(r + g + 8) * SPAD + k16 + ti * 2 + 8];
                al[0] = *(const uint32_t*)&sAl[(r + g    ) * SPAD + k16 + ti * 2];
                al[1] = *(const uint32_t*)&sAl[(r + g + 8) * SPAD + k16 + ti * 2];
                al[2] = *(const uint32_t*)&sAl[(r + g    ) * SPAD + k16 + ti * 2 + 8];
                al[3] = *(const uint32_t*)&sAl[(r + g + 8) * SPAD + k16 + ti * 2 + 8];
                #pragma unroll
                for (int nf = 0; nf < 4; nf++) {
                    mma16816(acc[mf][nf], ah, bh[nf]);
                    mma16816(acc[mf][nf], ah, bl[nf]);
                    mma16816(acc[mf][nf], al, bh[nf]);
                }
            }
        }
        __syncthreads();
    }

    #pragma unroll
    for (int mf = 0; mf < 4; mf++) {
        int r0 = m0 + wm * 64 + mf * 16 + g;
        #pragma unroll
        for (int nf = 0; nf < 4; nf++) {
            int col = n0 + wn * 32 + nf * 8 + ti * 2;
            float2 bv = *(const float2*)(bias + col);
            float o00 = acc[mf][nf][0] + bv.x, o01 = acc[mf][nf][1] + bv.y;
            float o10 = acc[mf][nf][2] + bv.x, o11 = acc[mf][nf][3] + bv.y;
            if (SPLIT) {
                __nv_bfloat16 h0, h1, l0b, l1b;
                split1(o00, h0, l0b); split1(o01, h1, l1b);
                *(__nv_bfloat162*)(Ch + (size_t)r0 * N + col) = __nv_bfloat162(h0, h1);
                *(__nv_bfloat162*)(Cl + (size_t)r0 * N + col) = __nv_bfloat162(l0b, l1b);
                split1(o10, h0, l0b); split1(o11, h1, l1b);
                *(__nv_bfloat162*)(Ch + (size_t)(r0 + 8) * N + col) = __nv_bfloat162(h0, h1);
                *(__nv_bfloat162*)(Cl + (size_t)(r0 + 8) * N + col) = __nv_bfloat162(l0b, l1b);
            } else {
                *(float2*)(C + (size_t)r0 * N + col)       = make_float2(o00, o01);
                *(float2*)(C + (size_t)(r0 + 8) * N + col) = make_float2(o10, o11);
            }
        }
    }
}

// ---------------------------------------------------------------------------
// Tensor-core flash attention, split-bf16, P in registers, cp.async pipeline.
// Block = (qt 64 rows, h, b); 128 threads = 4 warps x 16 q-rows.
// Writes hi/lo bf16 output directly.
// ---------------------------------------------------------------------------
#define APAD 72
#define AARR (64 * APAD)                 // 4608 elems per array
#define ASTG (4 * AARR)                  // per stage
#define ATTN_SMEM (2 * ASTG * 2)         // bytes = 73728
#define NT (SS / 64)

__global__ __launch_bounds__(128) void attn_mma(
    const __nv_bfloat16* __restrict__ qg_h, const __nv_bfloat16* __restrict__ qg_l,
    __nv_bfloat16* __restrict__ oh, __nv_bfloat16* __restrict__ ol)
{
    extern __shared__ __align__(16) __nv_bfloat16 adsm[];

    const int tid = threadIdx.x;
    const int wid = tid >> 5, lane = tid & 31;
    const int g = lane >> 2, ti = lane & 3;
    const int qt = blockIdx.x, h = blockIdx.y, b = blockIdx.z;
    const int h64 = h * DH;
    const size_t qrow0 = (size_t)(b * SS + qt * 64);

    const int lrow = tid >> 3;           // 0..15 (x4)
    const int lc8  = (tid & 7) * 8;

    auto issue = [&](int kt, int s) {
        __nv_bfloat16* base = adsm + s * ASTG;
        const size_t krow0 = (size_t)(b * SS + kt * 64);
        #pragma unroll
        for (int i = 0; i < 4; i++) {
            int row = lrow + i * 16;
            int off = row * APAD + lc8;
            size_t gk = (krow0 + row) * E3 +     EE + h64 + lc8;
            size_t gv = (krow0 + row) * E3 + 2 * EE + h64 + lc8;
            cpa16(s2u(base + off),            qg_h + gk);
            cpa16(s2u(base + AARR + off),     qg_l + gk);
            cpa16(s2u(base + 2 * AARR + off), qg_h + gv);
            cpa16(s2u(base + 3 * AARR + off), qg_l + gv);
        }
    };

    // prefetch KV tile 0 into stage 0 while staging Q in stage 1
    issue(0, 0); CPA_COMMIT();

    {
        __nv_bfloat16* qbh = adsm + ASTG;           // stage1 Kh slot
        __nv_bfloat16* qbl = adsm + ASTG + AARR;    // stage1 Kl slot
        #pragma unroll
        for (int i = 0; i < 4; i++) {
            int row = lrow + i * 16;
            size_t go = (qrow0 + row) * E3 + h64 + lc8;
            *(uint4*)(qbh + row * APAD + lc8) = *(const uint4*)(qg_h + go);
            *(uint4*)(qbl + row * APAD + lc8) = *(const uint4*)(qg_l + go);
        }
    }
    __syncthreads();
    uint32_t qh[4][4], ql[4][4];
    {
        const __nv_bfloat16* qbh = adsm + ASTG;
        const __nv_bfloat16* qbl = adsm + ASTG + AARR;
        #pragma unroll
        for (int ks = 0; ks < 4; ks++) {
            int k16 = ks * 16;
            int r = wid * 16;
            qh[ks][0] = *(const uint32_t*)&qbh[(r + g    ) * APAD + k16 + 2 * ti];
            qh[ks][1] = *(const uint32_t*)&qbh[(r + g + 8) * APAD + k16 + 2 * ti];
            qh[ks][2] = *(const uint32_t*)&qbh[(r + g    ) * APAD + k16 + 8 + 2 * ti];
            qh[ks][3] = *(const uint32_t*)&qbh[(r + g + 8) * APAD + k16 + 8 + 2 * ti];
            ql[ks][0] = *(const uint32_t*)&qbl[(r + g    ) * APAD + k16 + 2 * ti];
            ql[ks][1] = *(const uint32_t*)&qbl[(r + g + 8) * APAD + k16 + 2 * ti];
            ql[ks][2] = *(const uint32_t*)&qbl[(r + g    ) * APAD + k16 + 8 + 2 * ti];
            ql[ks][3] = *(const uint32_t*)&qbl[(r + g + 8) * APAD + k16 + 8 + 2 * ti];
        }
    }
    __syncthreads();

    float m0 = -1e30f, m1 = -1e30f, l0 = 0.f, l1 = 0.f;
    float accO[8][4] = {};
    const float scale = 0.125f;

    for (int kt = 0; kt < NT; kt++) {
        if (kt + 1 < NT) { issue(kt + 1, (kt + 1) & 1); CPA_COMMIT(); CPA_WAIT(1); }
        else             { CPA_WAIT(0); }
        __syncthreads();

        const __nv_bfloat16* sKh = adsm + (kt & 1) * ASTG;
        const __nv_bfloat16* sKl = sKh + AARR;
        const __nv_bfloat16* sVh = sKh + 2 * AARR;
        const __nv_bfloat16* sVl = sKh + 3 * AARR;

        // S = Q K^T (3-term split)
        float sacc[8][4] = {};
        #pragma unroll
        for (int ks = 0; ks < 4; ks++) {
            int k16 = ks * 16;
            #pragma unroll
            for (int nf = 0; nf < 8; nf++) {
                int r = nf * 8 + g;
                uint32_t kb[2], klb[2];
                kb[0]  = *(const uint32_t*)&sKh[r * APAD + k16 + 2 * ti];
                kb[1]  = *(const uint32_t*)&sKh[r * APAD + k16 + 8 + 2 * ti];
                klb[0] = *(const uint32_t*)&sKl[r * APAD + k16 + 2 * ti];
                klb[1] = *(const uint32_t*)&sKl[r * APAD + k16 + 8 + 2 * ti];
                mma16816(sacc[nf], qh[ks], kb);
                mma16816(sacc[nf], qh[ks], klb);
                mma16816(sacc[nf], ql[ks], kb);
            }
        }

        // online softmax
        float mx0 = -1e30f, mx1 = -1e30f;
        #pragma unroll
        for (int nf = 0; nf < 8; nf++) {
            sacc[nf][0] *= scale; sacc[nf][1] *= scale;
            sacc[nf][2] *= scale; sacc[nf][3] *= scale;
            mx0 = fmaxf(mx0, fmaxf(sacc[nf][0], sacc[nf][1]));
            mx1 = fmaxf(mx1, fmaxf(sacc[nf][2], sacc[nf][3]));
        }
        mx0 = fmaxf(mx0, __shfl_xor_sync(0xffffffffu, mx0, 1));
        mx0 = fmaxf(mx0, __shfl_xor_sync(0xffffffffu, mx0, 2));
        mx1 = fmaxf(mx1, __shfl_xor_sync(0xffffffffu, mx1, 1));
        mx1 = fmaxf(mx1, __shfl_xor_sync(0xffffffffu, mx1, 2));
        float mn0 = fmaxf(m0, mx0), mn1 = fmaxf(m1, mx1);
        float c0 = __expf(m0 - mn0), c1 = __expf(m1 - mn1);
        float rs0 = 0.f, rs1 = 0.f;
        #pragma unroll
        for (int nf = 0; nf < 8; nf++) {
            sacc[nf][0] = __expf(sacc[nf][0] - mn0);
            sacc[nf][1] = __expf(sacc[nf][1] - mn0);
            sacc[nf][2] = __expf(sacc[nf][2] - mn1);
            sacc[nf][3] = __expf(sacc[nf][3] - mn1);
            rs0 += sacc[nf][0] + sacc[nf][1];
            rs1 += sacc[nf][2] + sacc[nf][3];
        }
        rs0 += __shfl_xor_sync(0xffffffffu, rs0, 1);
        rs0 += __shfl_xor_sync(0xffffffffu, rs0, 2);
        rs1 += __shfl_xor_sync(0xffffffffu, rs1, 1);
        rs1 += __shfl_xor_sync(0xffffffffu, rs1, 2);
        l0 = l0 * c0 + rs0; l1 = l1 * c1 + rs1;
        m0 = mn0; m1 = mn1;
        #pragma unroll
        for (int nf = 0; nf < 8; nf++) {
            accO[nf][0] *= c0; accO[nf][1] *= c0;
            accO[nf][2] *= c1; accO[nf][3] *= c1;
        }

        // O += P V (P hi/lo in regs, V hi/lo via ldmatrix.trans)
        #pragma unroll
        for (int ks2 = 0; ks2 < 4; ks2++) {
            const int f0 = 2 * ks2, f1 = 2 * ks2 + 1;
            __nv_bfloat16 ph[8], plo[8];
            split1(sacc[f0][0], ph[0], plo[0]); split1(sacc[f0][1], ph[1], plo[1]);
            split1(sacc[f0][2], ph[2], plo[2]); split1(sacc[f0][3], ph[3], plo[3]);
            split1(sacc[f1][0], ph[4], plo[4]); split1(sacc[f1][1], ph[5], plo[5]);
            split1(sacc[f1][2], ph[6], plo[6]); split1(sacc[f1][3], ph[7], plo[7]);
            uint32_t pa[4], pl[4];
            pa[0] = pack2(ph[0], ph[1]);  pa[1] = pack2(ph[2], ph[3]);
            pa[2] = pack2(ph[4], ph[5]);  pa[3] = pack2(ph[6], ph[7]);
            pl[0] = pack2(plo[0], plo[1]); pl[1] = pack2(plo[2], plo[3]);
            pl[2] = pack2(plo[4], plo[5]); pl[3] = pack2(plo[6], plo[7]);

            const int k16 = ks2 * 16;
            const int quad = lane >> 3;
            const int vrow = k16 + (lane & 7) + (quad & 1) * 8;
            #pragma unroll
            for (int np = 0; np < 4; np++) {
                const int vcol = np * 16 + (quad >> 1) * 8;
                uint32_t vb[4], vlb[4];
                ldsm4t(vb,  s2u(&sVh[vrow * APAD + vcol]));
                ldsm4t(vlb, s2u(&sVl[vrow * APAD + vcol]));
                mma16816(accO[np*2],     pa, vb);
                mma16816(accO[np*2],     pa, vlb);
                mma16816(accO[np*2],     pl, vb);
                mma16816(accO[np*2 + 1], pa, vb + 2);
                mma16816(accO[np*2 + 1], pa, vlb + 2);
                mma16816(accO[np*2 + 1], pl, vb + 2);
            }
        }
        __syncthreads();
    }

    // epilogue: normalize, split to hi/lo bf16
    const float inv0 = 1.0f / l0, inv1 = 1.0f / l1;
    const size_t r0 = qrow0 + wid * 16 + g;
    #pragma unroll
    for (int nf = 0; nf < 8; nf++) {
        int col = h64 + nf * 8 + 2 * ti;
        float o00 = accO[nf][0] * inv0, o01 = accO[nf][1] * inv0;
        float o10 = accO[nf][2] * inv1, o11 = accO[nf][3] * inv1;
        __nv_bfloat16 hh0, hh1, ll0, ll1;
        split1(o00, hh0, ll0); split1(o01, hh1, ll1);
        *(__nv_bfloat162*)(oh + r0 * EE + col) = __nv_bfloat162(hh0, hh1);
        *(__nv_bfloat162*)(ol + r0 * EE + col) = __nv_bfloat162(ll0, ll1);
        split1(o10, hh0, ll0); split1(o11, hh1, ll1);
        *(__nv_bfloat162*)(oh + (r0 + 8) * EE + col) = __nv_bfloat162(hh0, hh1);
        *(__nv_bfloat162*)(ol + (r0 + 8) * EE + col) = __nv_bfloat162(ll0, ll1);
    }
}

// ---------------------------------------------------------------------------
extern "C" void kernel_launch(void* const* d_in, const int* in_sizes, int n_in,
                              void* d_out, int out_size)
{
    const float* x     = (const float*)d_in[0];
    const float* w_in  = (const float*)d_in[1];
    const float* b_in  = (const float*)d_in[2];
    const float* w_out = (const float*)d_in[3];
    const float* b_out = (const float*)d_in[4];
    float* out = (float*)d_out;

    __nv_bfloat16 *xh, *xl, *wih, *wil, *woh, *wol, *ah, *al, *qkh, *qkl;
    cudaGetSymbolAddress((void**)&xh,  g_x_hi);   cudaGetSymbolAddress((void**)&xl,  g_x_lo);
    cudaGetSymbolAddress((void**)&wih, g_wi_hi);  cudaGetSymbolAddress((void**)&wil, g_wi_lo);
    cudaGetSymbolAddress((void**)&woh, g_wo_hi);  cudaGetSymbolAddress((void**)&wol, g_wo_lo);
    cudaGetSymbolAddress((void**)&ah,  g_a_hi);   cudaGetSymbolAddress((void**)&al,  g_a_lo);
    cudaGetSymbolAddress((void**)&qkh, g_qkv_hi); cudaGetSymbolAddress((void**)&qkl, g_qkv_lo);

    cudaFuncSetAttribute(gemm_mma<true>,  cudaFuncAttributeMaxDynamicSharedMemorySize, GEMM_SMEM);
    cudaFuncSetAttribute(gemm_mma<false>, cudaFuncAttributeMaxDynamicSharedMemorySize, GEMM_SMEM);
    cudaFuncSetAttribute(attn_mma,        cudaFuncAttributeMaxDynamicSharedMemorySize, ATTN_SMEM);

    // 1) split inputs
    split_kernel<<<(MM * EE / 4 + 255) / 256, 256>>>(x,     xh,  xl,  MM * EE / 4);
    split_kernel<<<(E3 * EE / 4 + 255) / 256, 256>>>(w_in,  wih, wil, E3 * EE / 4);
    split_kernel<<<(EE * EE / 4 + 255) / 256, 256>>>(w_out, woh, wol, EE * EE / 4);

    // 2) QKV projection -> split bf16 qkv directly
    gemm_mma<true><<<dim3(E3 / 128, MM / 128), 256, GEMM_SMEM>>>(
        xh, xl, wih, wil, b_in, nullptr, qkh, qkl, E3, EE);

    // 3) attention -> split bf16 output directly
    attn_mma<<<dim3(SS / 64, HH, BB), 128, ATTN_SMEM>>>(qkh, qkl, ah, al);

    // 4) out projection -> fp32 final
    gemm_mma<false><<<dim3(EE / 128, MM / 128), 256, GEMM_SMEM>>>(
        ah, al, woh, wol, b_out, out, nullptr, nullptr, EE, EE);
}

// round 7
// speedup vs baseline: 3.1627x; 1.0354x over previous
#include <cuda_runtime.h>
#include <cuda_bf16.h>
#include <math.h>
#include <stdint.h>

#define BB   2
#define SS   2048
#define EE   1024
#define E3   3072
#define HH   16
#define DH   64
#define MM   (BB*SS)   // 4096

// ---------------------------------------------------------------------------
// Scratch (__device__ globals; no allocs allowed)
// ---------------------------------------------------------------------------
__device__ __nv_bfloat16 g_x_hi [MM * EE], g_x_lo [MM * EE];
__device__ __nv_bfloat16 g_wi_hi[E3 * EE], g_wi_lo[E3 * EE];
__device__ __nv_bfloat16 g_wo_hi[EE * EE], g_wo_lo[EE * EE];
__device__ __nv_bfloat16 g_a_hi [MM * EE], g_a_lo [MM * EE];
__device__ __nv_bfloat16 g_qkv_hi[MM * E3], g_qkv_lo[MM * E3];

// ---------------------------------------------------------------------------
// helpers
// ---------------------------------------------------------------------------
__device__ __forceinline__ void mma16816(float* d, const uint32_t* a, const uint32_t* b) {
    asm volatile(
        "mma.sync.aligned.m16n8k16.row.col.f32.bf16.bf16.f32 "
        "{%0,%1,%2,%3}, {%4,%5,%6,%7}, {%8,%9}, {%0,%1,%2,%3};"
        : "+f"(d[0]), "+f"(d[1]), "+f"(d[2]), "+f"(d[3])
        : "r"(a[0]), "r"(a[1]), "r"(a[2]), "r"(a[3]), "r"(b[0]), "r"(b[1]));
}
__device__ __forceinline__ void ldsm4(uint32_t* r, uint32_t saddr) {
    asm volatile("ldmatrix.sync.aligned.m8n8.x4.shared.b16 {%0,%1,%2,%3}, [%4];"
        : "=r"(r[0]), "=r"(r[1]), "=r"(r[2]), "=r"(r[3]) : "r"(saddr));
}
__device__ __forceinline__ void ldsm4t(uint32_t* r, uint32_t saddr) {
    asm volatile("ldmatrix.sync.aligned.m8n8.x4.trans.shared.b16 {%0,%1,%2,%3}, [%4];"
        : "=r"(r[0]), "=r"(r[1]), "=r"(r[2]), "=r"(r[3]) : "r"(saddr));
}
__device__ __forceinline__ uint32_t s2u(const void* p) {
    return (uint32_t)__cvta_generic_to_shared(p);
}
__device__ __forceinline__ uint32_t pack2(__nv_bfloat16 a, __nv_bfloat16 b) {
    __nv_bfloat162 t(a, b);
    return *(uint32_t*)&t;
}
__device__ __forceinline__ void cpa16(uint32_t s, const void* g) {
    asm volatile("cp.async.cg.shared.global [%0], [%1], 16;" :: "r"(s), "l"(g));
}
#define CPA_COMMIT()  asm volatile("cp.async.commit_group;" ::: "memory")
#define CPA_WAIT(n)   asm volatile("cp.async.wait_group %0;" :: "n"(n) : "memory")

__device__ __forceinline__ void split1(float v, __nv_bfloat16& h, __nv_bfloat16& l) {
    h = __float2bfloat16(v);
    l = __float2bfloat16(v - __bfloat162float(h));
}

// ---------------------------------------------------------------------------
// fp32 -> (hi, lo) bf16 split (inputs only)
// ---------------------------------------------------------------------------
__global__ __launch_bounds__(256) void split_kernel(
    const float* __restrict__ in, __nv_bfloat16* __restrict__ hi,
    __nv_bfloat16* __restrict__ lo, int n4)
{
    int i = blockIdx.x * blockDim.x + threadIdx.x;
    if (i >= n4) return;
    float4 v = ((const float4*)in)[i];
    __nv_bfloat16 hx, hy, hz, hw, lx, ly, lz, lw;
    split1(v.x, hx, lx); split1(v.y, hy, ly);
    split1(v.z, hz, lz); split1(v.w, hw, lw);
    __nv_bfloat162* h2 = (__nv_bfloat162*)hi;
    __nv_bfloat162* l2 = (__nv_bfloat162*)lo;
    h2[2*i]   = __nv_bfloat162(hx, hy);
    h2[2*i+1] = __nv_bfloat162(hz, hw);
    l2[2*i]   = __nv_bfloat162(lx, ly);
    l2[2*i+1] = __nv_bfloat162(lz, lw);
}

// ---------------------------------------------------------------------------
// Split-bf16 HMMA GEMM, cp.async 2-stage pipeline, ldmatrix fragment loads.
// BM=BN=128, BK=32, 256 thr (2m x 4n warps), warp tile 64x32.
// ---------------------------------------------------------------------------
#define SPAD 40
#define GARR (128 * SPAD)
#define GSTG (4 * GARR)
#define GEMM_SMEM (2 * GSTG * 2)

template<bool SPLIT>
__global__ __launch_bounds__(256, 2) void gemm_mma(
    const __nv_bfloat16* __restrict__ Ahi, const __nv_bfloat16* __restrict__ Alo,
    const __nv_bfloat16* __restrict__ Bhi, const __nv_bfloat16* __restrict__ Blo,
    const float* __restrict__ bias, float* __restrict__ C,
    __nv_bfloat16* __restrict__ Ch, __nv_bfloat16* __restrict__ Cl,
    int N, int K)
{
    extern __shared__ __align__(16) __nv_bfloat16 dsm[];

    const int tid  = threadIdx.x;
    const int wid  = tid >> 5, lane = tid & 31;
    const int wm   = wid & 1, wn = wid >> 1;
    const int g    = lane >> 2, ti = lane & 3;
    const int m0   = blockIdx.y * 128, n0 = blockIdx.x * 128;

    const int lrow = tid >> 2;
    const int lkq  = (tid & 3) * 8;

    // ldmatrix lane address components
    const int a_r = lane & 15, a_c = (lane >> 4) * 8;          // A frag
    const int b_i = lane & 7,  b_seg = lane >> 3;              // B frag
    const int b_rofs = (b_seg >> 1) * 8 + b_i, b_cofs = (b_seg & 1) * 8;

    auto issue = [&](int kc, int s) {
        __nv_bfloat16* base = dsm + s * GSTG;
        const int kb = kc * 32;
        #pragma unroll
        for (int i = 0; i < 2; i++) {
            int row = lrow + i * 64;
            int off = row * SPAD + lkq;
            size_t gA = (size_t)(m0 + row) * K + kb + lkq;
            size_t gB = (size_t)(n0 + row) * K + kb + lkq;
            cpa16(s2u(base + off),            Ahi + gA);
            cpa16(s2u(base + GARR + off),     Alo + gA);
            cpa16(s2u(base + 2 * GARR + off), Bhi + gB);
            cpa16(s2u(base + 3 * GARR + off), Blo + gB);
        }
    };

    float acc[4][4][4] = {};
    const int nchunk = K >> 5;

    issue(0, 0); CPA_COMMIT();

    for (int kc = 0; kc < nchunk; kc++) {
        if (kc + 1 < nchunk) { issue(kc + 1, (kc + 1) & 1); CPA_COMMIT(); CPA_WAIT(1); }
        else                 { CPA_WAIT(0); }
        __syncthreads();

        const __nv_bfloat16* sAh = dsm + (kc & 1) * GSTG;
        const __nv_bfloat16* sAl = sAh + GARR;
        const __nv_bfloat16* sBh = sAh + 2 * GARR;
        const __nv_bfloat16* sBl = sAh + 3 * GARR;

        #pragma unroll
        for (int ks = 0; ks < 2; ks++) {
            const int k16 = ks * 16;
            // B frags: 2 x ldmatrix.x4 per term -> 4 nf fragments
            uint32_t bh[4][2], bl[4][2];
            #pragma unroll
            for (int nfp = 0; nfp < 2; nfp++) {
                int r = wn * 32 + nfp * 16 + b_rofs;
                uint32_t t[4];
                ldsm4(t, s2u(&sBh[r * SPAD + k16 + b_cofs]));
                bh[2*nfp][0] = t[0]; bh[2*nfp][1] = t[1];
                bh[2*nfp+1][0] = t[2]; bh[2*nfp+1][1] = t[3];
                ldsm4(t, s2u(&sBl[r * SPAD + k16 + b_cofs]));
                bl[2*nfp][0] = t[0]; bl[2*nfp][1] = t[1];
                bl[2*nfp+1][0] = t[2]; bl[2*nfp+1][1] = t[3];
            }
            #pragma unroll
            for (int mf = 0; mf < 4; mf++) {
                int r = wm * 64 + mf * 16 + a_r;
                uint32_t ah[4], al[4];
                ldsm4(ah, s2u(&sAh[r * SPAD + k16 + a_c]));
                ldsm4(al, s2u(&sAl[r * SPAD + k16 + a_c]));
                #pragma unroll
                for (int nf = 0; nf < 4; nf++) {
                    mma16816(acc[mf][nf], ah, bh[nf]);
                    mma16816(acc[mf][nf], ah, bl[nf]);
                    mma16816(acc[mf][nf], al, bh[nf]);
                }
            }
        }
        __syncthreads();
    }

    #pragma unroll
    for (int mf = 0; mf < 4; mf++) {
        int r0 = m0 + wm * 64 + mf * 16 + g;
        #pragma unroll
        for (int nf = 0; nf < 4; nf++) {
            int col = n0 + wn * 32 + nf * 8 + ti * 2;
            float2 bv = *(const float2*)(bias + col);
            float o00 = acc[mf][nf][0] + bv.x, o01 = acc[mf][nf][1] + bv.y;
            float o10 = acc[mf][nf][2] + bv.x, o11 = acc[mf][nf][3] + bv.y;
            if (SPLIT) {
                __nv_bfloat16 h0, h1, l0b, l1b;
                split1(o00, h0, l0b); split1(o01, h1, l1b);
                *(__nv_bfloat162*)(Ch + (size_t)r0 * N + col) = __nv_bfloat162(h0, h1);
                *(__nv_bfloat162*)(Cl + (size_t)r0 * N + col) = __nv_bfloat162(l0b, l1b);
                split1(o10, h0, l0b); split1(o11, h1, l1b);
                *(__nv_bfloat162*)(Ch + (size_t)(r0 + 8) * N + col) = __nv_bfloat162(h0, h1);
                *(__nv_bfloat162*)(Cl + (size_t)(r0 + 8) * N + col) = __nv_bfloat162(l0b, l1b);
            } else {
                *(float2*)(C + (size_t)r0 * N + col)       = make_float2(o00, o01);
                *(float2*)(C + (size_t)(r0 + 8) * N + col) = make_float2(o10, o11);
            }
        }
    }
}

// ---------------------------------------------------------------------------
// Tensor-core flash attention, split-bf16, P in regs, cp.async + ldmatrix.
// Block = (qt 64 rows, h, b); 128 threads = 4 warps x 16 q-rows.
// ---------------------------------------------------------------------------
#define APAD 72
#define AARR (64 * APAD)
#define ASTG (4 * AARR)
#define ATTN_SMEM (2 * ASTG * 2)
#define NT (SS / 64)

__global__ __launch_bounds__(128) void attn_mma(
    const __nv_bfloat16* __restrict__ qg_h, const __nv_bfloat16* __restrict__ qg_l,
    __nv_bfloat16* __restrict__ oh, __nv_bfloat16* __restrict__ ol)
{
    extern __shared__ __align__(16) __nv_bfloat16 adsm[];

    const int tid = threadIdx.x;
    const int wid = tid >> 5, lane = tid & 31;
    const int g = lane >> 2, ti = lane & 3;
    const int qt = blockIdx.x, h = blockIdx.y, b = blockIdx.z;
    const int h64 = h * DH;
    const size_t qrow0 = (size_t)(b * SS + qt * 64);

    const int lrow = tid >> 3;
    const int lc8  = (tid & 7) * 8;

    // ldmatrix lane address components (B-style, for K frags)
    const int b_i = lane & 7, b_seg = lane >> 3;
    const int b_rofs = (b_seg >> 1) * 8 + b_i, b_cofs = (b_seg & 1) * 8;

    auto issue = [&](int kt, int s) {
        __nv_bfloat16* base = adsm + s * ASTG;
        const size_t krow0 = (size_t)(b * SS + kt * 64);
        #pragma unroll
        for (int i = 0; i < 4; i++) {
            int row = lrow + i * 16;
            int off = row * APAD + lc8;
            size_t gk = (krow0 + row) * E3 +     EE + h64 + lc8;
            size_t gv = (krow0 + row) * E3 + 2 * EE + h64 + lc8;
            cpa16(s2u(base + off),            qg_h + gk);
            cpa16(s2u(base + AARR + off),     qg_l + gk);
            cpa16(s2u(base + 2 * AARR + off), qg_h + gv);
            cpa16(s2u(base + 3 * AARR + off), qg_l + gv);
        }
    };

    issue(0, 0); CPA_COMMIT();

    {
        __nv_bfloat16* qbh = adsm + ASTG;
        __nv_bfloat16* qbl = adsm + ASTG + AARR;
        #pragma unroll
        for (int i = 0; i < 4; i++) {
            int row = lrow + i * 16;
            size_t go = (qrow0 + row) * E3 + h64 + lc8;
            *(uint4*)(qbh + row * APAD + lc8) = *(const uint4*)(qg_h + go);
            *(uint4*)(qbl + row * APAD + lc8) = *(const uint4*)(qg_l + go);
        }
    }
    __syncthreads();
    uint32_t qh[4][4], ql[4][4];
    {
        const __nv_bfloat16* qbh = adsm + ASTG;
        const __nv_bfloat16* qbl = adsm + ASTG + AARR;
        const int a_r = lane & 15, a_c = (lane >> 4) * 8;
        #pragma unroll
        for (int ks = 0; ks < 4; ks++) {
            int k16 = ks * 16;
            int r = wid * 16 + a_r;
            ldsm4(qh[ks], s2u(&qbh[r * APAD + k16 + a_c]));
            ldsm4(ql[ks], s2u(&qbl[r * APAD + k16 + a_c]));
        }
    }
    __syncthreads();

    float m0 = -1e30f, m1 = -1e30f, l0 = 0.f, l1 = 0.f;
    float accO[8][4] = {};
    const float scale = 0.125f;

    for (int kt = 0; kt < NT; kt++) {
        if (kt + 1 < NT) { issue(kt + 1, (kt + 1) & 1); CPA_COMMIT(); CPA_WAIT(1); }
        else             { CPA_WAIT(0); }
        __syncthreads();

        const __nv_bfloat16* sKh = adsm + (kt & 1) * ASTG;
        const __nv_bfloat16* sKl = sKh + AARR;
        const __nv_bfloat16* sVh = sKh + 2 * AARR;
        const __nv_bfloat16* sVl = sKh + 3 * AARR;

        // S = Q K^T (3-term split), K frags via ldmatrix.x4 (2 nf per op)
        float sacc[8][4] = {};
        #pragma unroll
        for (int ks = 0; ks < 4; ks++) {
            int k16 = ks * 16;
            #pragma unroll
            for (int nfp = 0; nfp < 4; nfp++) {
                int r = nfp * 16 + b_rofs;
                uint32_t th[4], tl[4];
                ldsm4(th, s2u(&sKh[r * APAD + k16 + b_cofs]));
                ldsm4(tl, s2u(&sKl[r * APAD + k16 + b_cofs]));
                mma16816(sacc[2*nfp],     qh[ks], th);
                mma16816(sacc[2*nfp],     qh[ks], tl);
                mma16816(sacc[2*nfp],     ql[ks], th);
                mma16816(sacc[2*nfp + 1], qh[ks], th + 2);
                mma16816(sacc[2*nfp + 1], qh[ks], tl + 2);
                mma16816(sacc[2*nfp + 1], ql[ks], th + 2);
            }
        }

        // online softmax
        float mx0 = -1e30f, mx1 = -1e30f;
        #pragma unroll
        for (int nf = 0; nf < 8; nf++) {
            sacc[nf][0] *= scale; sacc[nf][1] *= scale;
            sacc[nf][2] *= scale; sacc[nf][3] *= scale;
            mx0 = fmaxf(mx0, fmaxf(sacc[nf][0], sacc[nf][1]));
            mx1 = fmaxf(mx1, fmaxf(sacc[nf][2], sacc[nf][3]));
        }
        mx0 = fmaxf(mx0, __shfl_xor_sync(0xffffffffu, mx0, 1));
        mx0 = fmaxf(mx0, __shfl_xor_sync(0xffffffffu, mx0, 2));
        mx1 = fmaxf(mx1, __shfl_xor_sync(0xffffffffu, mx1, 1));
        mx1 = fmaxf(mx1, __shfl_xor_sync(0xffffffffu, mx1, 2));
        float mn0 = fmaxf(m0, mx0), mn1 = fmaxf(m1, mx1);
        float c0 = __expf(m0 - mn0), c1 = __expf(m1 - mn1);
        float rs0 = 0.f, rs1 = 0.f;
        #pragma unroll
        for (int nf = 0; nf < 8; nf++) {
            sacc[nf][0] = __expf(sacc[nf][0] - mn0);
            sacc[nf][1] = __expf(sacc[nf][1] - mn0);
            sacc[nf][2] = __expf(sacc[nf][2] - mn1);
            sacc[nf][3] = __expf(sacc[nf][3] - mn1);
            rs0 += sacc[nf][0] + sacc[nf][1];
            rs1 += sacc[nf][2] + sacc[nf][3];
        }
        rs0 += __shfl_xor_sync(0xffffffffu, rs0, 1);
        rs0 += __shfl_xor_sync(0xffffffffu, rs0, 2);
        rs1 += __shfl_xor_sync(0xffffffffu, rs1, 1);
        rs1 += __shfl_xor_sync(0xffffffffu, rs1, 2);
        l0 = l0 * c0 + rs0; l1 = l1 * c1 + rs1;
        m0 = mn0; m1 = mn1;
        #pragma unroll
        for (int nf = 0; nf < 8; nf++) {
            accO[nf][0] *= c0; accO[nf][1] *= c0;
            accO[nf][2] *= c1; accO[nf][3] *= c1;
        }

        // O += P V
        #pragma unroll
        for (int ks2 = 0; ks2 < 4; ks2++) {
            const int f0 = 2 * ks2, f1 = 2 * ks2 + 1;
            __nv_bfloat16 ph[8], plo[8];
            split1(sacc[f0][0], ph[0], plo[0]); split1(sacc[f0][1], ph[1], plo[1]);
            split1(sacc[f0][2], ph[2], plo[2]); split1(sacc[f0][3], ph[3], plo[3]);
            split1(sacc[f1][0], ph[4], plo[4]); split1(sacc[f1][1], ph[5], plo[5]);
            split1(sacc[f1][2], ph[6], plo[6]); split1(sacc[f1][3], ph[7], plo[7]);
            uint32_t pa[4], pl[4];
            pa[0] = pack2(ph[0], ph[1]);  pa[1] = pack2(ph[2], ph[3]);
            pa[2] = pack2(ph[4], ph[5]);  pa[3] = pack2(ph[6], ph[7]);
            pl[0] = pack2(plo[0], plo[1]); pl[1] = pack2(plo[2], plo[3]);
            pl[2] = pack2(plo[4], plo[5]); pl[3] = pack2(plo[6], plo[7]);

            const int k16 = ks2 * 16;
            const int quad = lane >> 3;
            const int vrow = k16 + (lane & 7) + (quad & 1) * 8;
            #pragma unroll
            for (int np = 0; np < 4; np++) {
                const int vcol = np * 16 + (quad >> 1) * 8;
                uint32_t vb[4], vlb[4];
                ldsm4t(vb,  s2u(&sVh[vrow * APAD + vcol]));
                ldsm4t(vlb, s2u(&sVl[vrow * APAD + vcol]));
                mma16816(accO[np*2],     pa, vb);
                mma16816(accO[np*2],     pa, vlb);
                mma16816(accO[np*2],     pl, vb);
                mma16816(accO[np*2 + 1], pa, vb + 2);
                mma16816(accO[np*2 + 1], pa, vlb + 2);
                mma16816(accO[np*2 + 1], pl, vb + 2);
            }
        }
        __syncthreads();
    }

    const float inv0 = 1.0f / l0, inv1 = 1.0f / l1;
    const size_t r0 = qrow0 + wid * 16 + g;
    #pragma unroll
    for (int nf = 0; nf < 8; nf++) {
        int col = h64 + nf * 8 + 2 * ti;
        float o00 = accO[nf][0] * inv0, o01 = accO[nf][1] * inv0;
        float o10 = accO[nf][2] * inv1, o11 = accO[nf][3] * inv1;
        __nv_bfloat16 hh0, hh1, ll0, ll1;
        split1(o00, hh0, ll0); split1(o01, hh1, ll1);
        *(__nv_bfloat162*)(oh + r0 * EE + col) = __nv_bfloat162(hh0, hh1);
        *(__nv_bfloat162*)(ol + r0 * EE + col) = __nv_bfloat162(ll0, ll1);
        split1(o10, hh0, ll0); split1(o11, hh1, ll1);
        *(__nv_bfloat162*)(oh + (r0 + 8) * EE + col) = __nv_bfloat162(hh0, hh1);
        *(__nv_bfloat162*)(ol + (r0 + 8) * EE + col) = __nv_bfloat162(ll0, ll1);
    }
}

// ---------------------------------------------------------------------------
extern "C" void kernel_launch(void* const* d_in, const int* in_sizes, int n_in,
                              void* d_out, int out_size)
{
    const float* x     = (const float*)d_in[0];
    const float* w_in  = (const float*)d_in[1];
    const float* b_in  = (const float*)d_in[2];
    const float* w_out = (const float*)d_in[3];
    const float* b_out = (const float*)d_in[4];
    float* out = (float*)d_out;

    __nv_bfloat16 *xh, *xl, *wih, *wil, *woh, *wol, *ah, *al, *qkh, *qkl;
    cudaGetSymbolAddress((void**)&xh,  g_x_hi);   cudaGetSymbolAddress((void**)&xl,  g_x_lo);
    cudaGetSymbolAddress((void**)&wih, g_wi_hi);  cudaGetSymbolAddress((void**)&wil, g_wi_lo);
    cudaGetSymbolAddress((void**)&woh, g_wo_hi);  cudaGetSymbolAddress((void**)&wol, g_wo_lo);
    cudaGetSymbolAddress((void**)&ah,  g_a_hi);   cudaGetSymbolAddress((void**)&al,  g_a_lo);
    cudaGetSymbolAddress((void**)&qkh, g_qkv_hi); cudaGetSymbolAddress((void**)&qkl, g_qkv_lo);

    cudaFuncSetAttribute(gemm_mma<true>,  cudaFuncAttributeMaxDynamicSharedMemorySize, GEMM_SMEM);
    cudaFuncSetAttribute(gemm_mma<false>, cudaFuncAttributeMaxDynamicSharedMemorySize, GEMM_SMEM);
    cudaFuncSetAttribute(attn_mma,        cudaFuncAttributeMaxDynamicSharedMemorySize, ATTN_SMEM);

    split_kernel<<<(MM * EE / 4 + 255) / 256, 256>>>(x,     xh,  xl,  MM * EE / 4);
    split_kernel<<<(E3 * EE / 4 + 255) / 256, 256>>>(w_in,  wih, wil, E3 * EE / 4);
    split_kernel<<<(EE * EE / 4 + 255) / 256, 256>>>(w_out, woh, wol, EE * EE / 4);

    gemm_mma<true><<<dim3(E3 / 128, MM / 128), 256, GEMM_SMEM>>>(
        xh, xl, wih, wil, b_in, nullptr, qkh, qkl, E3, EE);

    attn_mma<<<dim3(SS / 64, HH, BB), 128, ATTN_SMEM>>>(qkh, qkl, ah, al);

    gemm_mma<false><<<dim3(EE / 128, MM / 128), 256, GEMM_SMEM>>>(
        ah, al, woh, wol, b_out, out, nullptr, nullptr, EE, EE);
}

// round 8
// speedup vs baseline: 3.6608x; 1.1575x over previous
#include <cuda_runtime.h>
#include <cuda_bf16.h>
#include <math.h>
#include <stdint.h>

#define BB   2
#define SS   2048
#define EE   1024
#define E3   3072
#define HH   16
#define DH   64
#define MM   (BB*SS)   // 4096

// ---------------------------------------------------------------------------
// Scratch (__device__ globals; no allocs allowed)
// ---------------------------------------------------------------------------
__device__ float g_x_t [MM * EE];          // tf32-rounded x
__device__ float g_wi_t[E3 * EE];          // tf32-rounded w_in
__device__ float g_wo_t[EE * EE];          // tf32-rounded w_out
__device__ float g_a_t [MM * EE];          // tf32-rounded attention output
__device__ __nv_bfloat16 g_qkv_hi[MM * E3], g_qkv_lo[MM * E3];

// ---------------------------------------------------------------------------
// helpers
// ---------------------------------------------------------------------------
__device__ __forceinline__ void mma16816(float* d, const uint32_t* a, const uint32_t* b) {
    asm volatile(
        "mma.sync.aligned.m16n8k16.row.col.f32.bf16.bf16.f32 "
        "{%0,%1,%2,%3}, {%4,%5,%6,%7}, {%8,%9}, {%0,%1,%2,%3};"
        : "+f"(d[0]), "+f"(d[1]), "+f"(d[2]), "+f"(d[3])
        : "r"(a[0]), "r"(a[1]), "r"(a[2]), "r"(a[3]), "r"(b[0]), "r"(b[1]));
}
__device__ __forceinline__ void mma_tf32(float* d, const uint32_t* a, const uint32_t* b) {
    asm volatile(
        "mma.sync.aligned.m16n8k8.row.col.f32.tf32.tf32.f32 "
        "{%0,%1,%2,%3}, {%4,%5,%6,%7}, {%8,%9}, {%0,%1,%2,%3};"
        : "+f"(d[0]), "+f"(d[1]), "+f"(d[2]), "+f"(d[3])
        : "r"(a[0]), "r"(a[1]), "r"(a[2]), "r"(a[3]), "r"(b[0]), "r"(b[1]));
}
__device__ __forceinline__ void ldsm4(uint32_t* r, uint32_t saddr) {
    asm volatile("ldmatrix.sync.aligned.m8n8.x4.shared.b16 {%0,%1,%2,%3}, [%4];"
        : "=r"(r[0]), "=r"(r[1]), "=r"(r[2]), "=r"(r[3]) : "r"(saddr));
}
__device__ __forceinline__ void ldsm4t(uint32_t* r, uint32_t saddr) {
    asm volatile("ldmatrix.sync.aligned.m8n8.x4.trans.shared.b16 {%0,%1,%2,%3}, [%4];"
        : "=r"(r[0]), "=r"(r[1]), "=r"(r[2]), "=r"(r[3]) : "r"(saddr));
}
__device__ __forceinline__ uint32_t s2u(const void* p) {
    return (uint32_t)__cvta_generic_to_shared(p);
}
__device__ __forceinline__ uint32_t pack2(__nv_bfloat16 a, __nv_bfloat16 b) {
    __nv_bfloat162 t(a, b);
    return *(uint32_t*)&t;
}
__device__ __forceinline__ void cpa16(uint32_t s, const void* g) {
    asm volatile("cp.async.cg.shared.global [%0], [%1], 16;" :: "r"(s), "l"(g));
}
#define CPA_COMMIT()  asm volatile("cp.async.commit_group;" ::: "memory")
#define CPA_WAIT(n)   asm volatile("cp.async.wait_group %0;" :: "n"(n) : "memory")

__device__ __forceinline__ void split1(float v, __nv_bfloat16& h, __nv_bfloat16& l) {
    h = __float2bfloat16(v);
    l = __float2bfloat16(v - __bfloat162float(h));
}
__device__ __forceinline__ float to_tf32(float v) {
    uint32_t r;
    asm("cvt.rna.tf32.f32 %0, %1;" : "=r"(r) : "f"(v));
    return __uint_as_float(r);
}

// ---------------------------------------------------------------------------
// fp32 -> tf32-rounded fp32 (inputs)
// ---------------------------------------------------------------------------
__global__ __launch_bounds__(256) void round_kernel(
    const float* __restrict__ in, float* __restrict__ outp, int n4)
{
    int i = blockIdx.x * blockDim.x + threadIdx.x;
    if (i >= n4) return;
    float4 v = ((const float4*)in)[i];
    v.x = to_tf32(v.x); v.y = to_tf32(v.y);
    v.z = to_tf32(v.z); v.w = to_tf32(v.w);
    ((float4*)outp)[i] = v;
}

// ---------------------------------------------------------------------------
// Single-pass TF32 GEMM: C[M,N] = A[M,K] @ W[N,K]^T + bias
// BM=BN=128, BK=32 (tf32), 256 thr (2m x 4n warps), warp tile 64x32.
// cp.async 2-stage pipeline; all fragments via ldmatrix (b16-as-tf32 trick).
// SPLIT=true: write bf16 hi/lo outputs (for bf16 attention); else fp32 C.
// ---------------------------------------------------------------------------
#define GP 36
#define GT (128 * GP)                      // words per array (4608)
#define GSTGW (2 * GT)                     // words per stage
#define GEMM_SMEM (2 * GSTGW * 4)          // 73728 bytes

template<bool SPLIT>
__global__ __launch_bounds__(256, 2) void gemm_tf32(
    const float* __restrict__ A, const float* __restrict__ Bw,
    const float* __restrict__ bias, float* __restrict__ C,
    __nv_bfloat16* __restrict__ Ch, __nv_bfloat16* __restrict__ Cl,
    int N, int K)
{
    extern __shared__ __align__(16) float dsm[];

    const int tid  = threadIdx.x;
    const int wid  = tid >> 5, lane = tid & 31;
    const int wm   = wid & 1, wn = wid >> 1;
    const int g    = lane >> 2, ti = lane & 3;
    const int m0   = blockIdx.y * 128, n0 = blockIdx.x * 128;

    // ldmatrix lane address components (tf32 word granularity)
    const int a_row = lane & 15;                      // A frag rows
    const int a_csel = (lane >> 4) * 4;               // A frag word offset (0 or 4)
    const int b_row = (lane & 7) + ((lane >> 4) * 8); // B frag rows
    const int b_csel = ((lane >> 3) & 1) * 4;         // B frag word offset

    auto issue = [&](int kc, int s) {
        float* base = dsm + s * GSTGW;
        const int kb = kc * 32;
        #pragma unroll
        for (int i = 0; i < 4; i++) {
            int idx = tid + i * 256;         // 0..1023
            int row = idx >> 3;
            int seg = (idx & 7) * 4;
            int off = row * GP + seg;
            cpa16(s2u(base + off),      A  + (size_t)(m0 + row) * K + kb + seg);
            cpa16(s2u(base + GT + off), Bw + (size_t)(n0 + row) * K + kb + seg);
        }
    };

    float acc[4][4][4] = {};
    const int nchunk = K >> 5;

    issue(0, 0); CPA_COMMIT();

    for (int kc = 0; kc < nchunk; kc++) {
        if (kc + 1 < nchunk) { issue(kc + 1, (kc + 1) & 1); CPA_COMMIT(); CPA_WAIT(1); }
        else                 { CPA_WAIT(0); }
        __syncthreads();

        const float* sA = dsm + (kc & 1) * GSTGW;
        const float* sB = sA + GT;

        #pragma unroll
        for (int ks = 0; ks < 4; ks++) {
            const int k0 = ks * 8;
            // B frags: 2 x ldmatrix.x4 -> 4 nf fragments
            uint32_t b[4][2];
            #pragma unroll
            for (int nfp = 0; nfp < 2; nfp++) {
                int r = wn * 32 + nfp * 16 + b_row;
                uint32_t t[4];
                ldsm4(t, s2u(&sB[r * GP + k0 + b_csel]));
                b[2*nfp][0] = t[0]; b[2*nfp][1] = t[1];
                b[2*nfp+1][0] = t[2]; b[2*nfp+1][1] = t[3];
            }
            #pragma unroll
            for (int mf = 0; mf < 4; mf++) {
                int r = wm * 64 + mf * 16 + a_row;
                uint32_t a[4];
                ldsm4(a, s2u(&sA[r * GP + k0 + a_csel]));
                #pragma unroll
                for (int nf = 0; nf < 4; nf++)
                    mma_tf32(acc[mf][nf], a, b[nf]);
            }
        }
        __syncthreads();
    }

    #pragma unroll
    for (int mf = 0; mf < 4; mf++) {
        int r0 = m0 + wm * 64 + mf * 16 + g;
        #pragma unroll
        for (int nf = 0; nf < 4; nf++) {
            int col = n0 + wn * 32 + nf * 8 + ti * 2;
            float2 bv = *(const float2*)(bias + col);
            float o00 = acc[mf][nf][0] + bv.x, o01 = acc[mf][nf][1] + bv.y;
            float o10 = acc[mf][nf][2] + bv.x, o11 = acc[mf][nf][3] + bv.y;
            if (SPLIT) {
                __nv_bfloat16 h0, h1, l0b, l1b;
                split1(o00, h0, l0b); split1(o01, h1, l1b);
                *(__nv_bfloat162*)(Ch + (size_t)r0 * N + col) = __nv_bfloat162(h0, h1);
                *(__nv_bfloat162*)(Cl + (size_t)r0 * N + col) = __nv_bfloat162(l0b, l1b);
                split1(o10, h0, l0b); split1(o11, h1, l1b);
                *(__nv_bfloat162*)(Ch + (size_t)(r0 + 8) * N + col) = __nv_bfloat162(h0, h1);
                *(__nv_bfloat162*)(Cl + (size_t)(r0 + 8) * N + col) = __nv_bfloat162(l0b, l1b);
            } else {
                *(float2*)(C + (size_t)r0 * N + col)       = make_float2(o00, o01);
                *(float2*)(C + (size_t)(r0 + 8) * N + col) = make_float2(o10, o11);
            }
        }
    }
}

// ---------------------------------------------------------------------------
// Tensor-core flash attention, split-bf16, P in regs, cp.async + ldmatrix.
// Block = (qt 64 rows, h, b); 128 threads = 4 warps x 16 q-rows.
// Epilogue writes tf32-rounded fp32 (input of the tf32 out-projection).
// ---------------------------------------------------------------------------
#define APAD 72
#define AARR (64 * APAD)
#define ASTG (4 * AARR)
#define ATTN_SMEM (2 * ASTG * 2)
#define NT (SS / 64)

__global__ __launch_bounds__(128) void attn_mma(
    const __nv_bfloat16* __restrict__ qg_h, const __nv_bfloat16* __restrict__ qg_l,
    float* __restrict__ ot)
{
    extern __shared__ __align__(16) __nv_bfloat16 adsm[];

    const int tid = threadIdx.x;
    const int wid = tid >> 5, lane = tid & 31;
    const int g = lane >> 2, ti = lane & 3;
    const int qt = blockIdx.x, h = blockIdx.y, b = blockIdx.z;
    const int h64 = h * DH;
    const size_t qrow0 = (size_t)(b * SS + qt * 64);

    const int lrow = tid >> 3;
    const int lc8  = (tid & 7) * 8;

    const int b_i = lane & 7, b_seg = lane >> 3;
    const int b_rofs = (b_seg >> 1) * 8 + b_i, b_cofs = (b_seg & 1) * 8;

    auto issue = [&](int kt, int s) {
        __nv_bfloat16* base = adsm + s * ASTG;
        const size_t krow0 = (size_t)(b * SS + kt * 64);
        #pragma unroll
        for (int i = 0; i < 4; i++) {
            int row = lrow + i * 16;
            int off = row * APAD + lc8;
            size_t gk = (krow0 + row) * E3 +     EE + h64 + lc8;
            size_t gv = (krow0 + row) * E3 + 2 * EE + h64 + lc8;
            cpa16(s2u(base + off),            qg_h + gk);
            cpa16(s2u(base + AARR + off),     qg_l + gk);
            cpa16(s2u(base + 2 * AARR + off), qg_h + gv);
            cpa16(s2u(base + 3 * AARR + off), qg_l + gv);
        }
    };

    issue(0, 0); CPA_COMMIT();

    {
        __nv_bfloat16* qbh = adsm + ASTG;
        __nv_bfloat16* qbl = adsm + ASTG + AARR;
        #pragma unroll
        for (int i = 0; i < 4; i++) {
            int row = lrow + i * 16;
            size_t go = (qrow0 + row) * E3 + h64 + lc8;
            *(uint4*)(qbh + row * APAD + lc8) = *(const uint4*)(qg_h + go);
            *(uint4*)(qbl + row * APAD + lc8) = *(const uint4*)(qg_l + go);
        }
    }
    __syncthreads();
    uint32_t qh[4][4], ql[4][4];
    {
        const __nv_bfloat16* qbh = adsm + ASTG;
        const __nv_bfloat16* qbl = adsm + ASTG + AARR;
        const int a_r = lane & 15, a_c = (lane >> 4) * 8;
        #pragma unroll
        for (int ks = 0; ks < 4; ks++) {
            int k16 = ks * 16;
            int r = wid * 16 + a_r;
            ldsm4(qh[ks], s2u(&qbh[r * APAD + k16 + a_c]));
            ldsm4(ql[ks], s2u(&qbl[r * APAD + k16 + a_c]));
        }
    }
    __syncthreads();

    float m0 = -1e30f, m1 = -1e30f, l0 = 0.f, l1 = 0.f;
    float accO[8][4] = {};
    const float scale = 0.125f;

    for (int kt = 0; kt < NT; kt++) {
        if (kt + 1 < NT) { issue(kt + 1, (kt + 1) & 1); CPA_COMMIT(); CPA_WAIT(1); }
        else             { CPA_WAIT(0); }
        __syncthreads();

        const __nv_bfloat16* sKh = adsm + (kt & 1) * ASTG;
        const __nv_bfloat16* sKl = sKh + AARR;
        const __nv_bfloat16* sVh = sKh + 2 * AARR;
        const __nv_bfloat16* sVl = sKh + 3 * AARR;

        float sacc[8][4] = {};
        #pragma unroll
        for (int ks = 0; ks < 4; ks++) {
            int k16 = ks * 16;
            #pragma unroll
            for (int nfp = 0; nfp < 4; nfp++) {
                int r = nfp * 16 + b_rofs;
                uint32_t th[4], tl[4];
                ldsm4(th, s2u(&sKh[r * APAD + k16 + b_cofs]));
                ldsm4(tl, s2u(&sKl[r * APAD + k16 + b_cofs]));
                mma16816(sacc[2*nfp],     qh[ks], th);
                mma16816(sacc[2*nfp],     qh[ks], tl);
                mma16816(sacc[2*nfp],     ql[ks], th);
                mma16816(sacc[2*nfp + 1], qh[ks], th + 2);
                mma16816(sacc[2*nfp + 1], qh[ks], tl + 2);
                mma16816(sacc[2*nfp + 1], ql[ks], th + 2);
            }
        }

        float mx0 = -1e30f, mx1 = -1e30f;
        #pragma unroll
        for (int nf = 0; nf < 8; nf++) {
            sacc[nf][0] *= scale; sacc[nf][1] *= scale;
            sacc[nf][2] *= scale; sacc[nf][3] *= scale;
            mx0 = fmaxf(mx0, fmaxf(sacc[nf][0], sacc[nf][1]));
            mx1 = fmaxf(mx1, fmaxf(sacc[nf][2], sacc[nf][3]));
        }
        mx0 = fmaxf(mx0, __shfl_xor_sync(0xffffffffu, mx0, 1));
        mx0 = fmaxf(mx0, __shfl_xor_sync(0xffffffffu, mx0, 2));
        mx1 = fmaxf(mx1, __shfl_xor_sync(0xffffffffu, mx1, 1));
        mx1 = fmaxf(mx1, __shfl_xor_sync(0xffffffffu, mx1, 2));
        float mn0 = fmaxf(m0, mx0), mn1 = fmaxf(m1, mx1);
        float c0 = __expf(m0 - mn0), c1 = __expf(m1 - mn1);
        float rs0 = 0.f, rs1 = 0.f;
        #pragma unroll
        for (int nf = 0; nf < 8; nf++) {
            sacc[nf][0] = __expf(sacc[nf][0] - mn0);
            sacc[nf][1] = __expf(sacc[nf][1] - mn0);
            sacc[nf][2] = __expf(sacc[nf][2] - mn1);
            sacc[nf][3] = __expf(sacc[nf][3] - mn1);
            rs0 += sacc[nf][0] + sacc[nf][1];
            rs1 += sacc[nf][2] + sacc[nf][3];
        }
        rs0 += __shfl_xor_sync(0xffffffffu, rs0, 1);
        rs0 += __shfl_xor_sync(0xffffffffu, rs0, 2);
        rs1 += __shfl_xor_sync(0xffffffffu, rs1, 1);
        rs1 += __shfl_xor_sync(0xffffffffu, rs1, 2);
        l0 = l0 * c0 + rs0; l1 = l1 * c1 + rs1;
        m0 = mn0; m1 = mn1;
        #pragma unroll
        for (int nf = 0; nf < 8; nf++) {
            accO[nf][0] *= c0; accO[nf][1] *= c0;
            accO[nf][2] *= c1; accO[nf][3] *= c1;
        }

        #pragma unroll
        for (int ks2 = 0; ks2 < 4; ks2++) {
            const int f0 = 2 * ks2, f1 = 2 * ks2 + 1;
            __nv_bfloat16 ph[8], plo[8];
            split1(sacc[f0][0], ph[0], plo[0]); split1(sacc[f0][1], ph[1], plo[1]);
            split1(sacc[f0][2], ph[2], plo[2]); split1(sacc[f0][3], ph[3], plo[3]);
            split1(sacc[f1][0], ph[4], plo[4]); split1(sacc[f1][1], ph[5], plo[5]);
            split1(sacc[f1][2], ph[6], plo[6]); split1(sacc[f1][3], ph[7], plo[7]);
            uint32_t pa[4], pl[4];
            pa[0] = pack2(ph[0], ph[1]);  pa[1] = pack2(ph[2], ph[3]);
            pa[2] = pack2(ph[4], ph[5]);  pa[3] = pack2(ph[6], ph[7]);
            pl[0] = pack2(plo[0], plo[1]); pl[1] = pack2(plo[2], plo[3]);
            pl[2] = pack2(plo[4], plo[5]); pl[3] = pack2(plo[6], plo[7]);

            const int k16 = ks2 * 16;
            const int quad = lane >> 3;
            const int vrow = k16 + (lane & 7) + (quad & 1) * 8;
            #pragma unroll
            for (int np = 0; np < 4; np++) {
                const int vcol = np * 16 + (quad >> 1) * 8;
                uint32_t vb[4], vlb[4];
                ldsm4t(vb,  s2u(&sVh[vrow * APAD + vcol]));
                ldsm4t(vlb, s2u(&sVl[vrow * APAD + vcol]));
                mma16816(accO[np*2],     pa, vb);
                mma16816(accO[np*2],     pa, vlb);
                mma16816(accO[np*2],     pl, vb);
                mma16816(accO[np*2 + 1], pa, vb + 2);
                mma16816(accO[np*2 + 1], pa, vlb + 2);
                mma16816(accO[np*2 + 1], pl, vb + 2);
            }
        }
        __syncthreads();
    }

    // epilogue: normalize, round to tf32, store fp32
    const float inv0 = 1.0f / l0, inv1 = 1.0f / l1;
    const size_t r0 = qrow0 + wid * 16 + g;
    #pragma unroll
    for (int nf = 0; nf < 8; nf++) {
        int col = h64 + nf * 8 + 2 * ti;
        float2 o0, o1;
        o0.x = to_tf32(accO[nf][0] * inv0); o0.y = to_tf32(accO[nf][1] * inv0);
        o1.x = to_tf32(accO[nf][2] * inv1); o1.y = to_tf32(accO[nf][3] * inv1);
        *(float2*)(ot + r0 * EE + col)       = o0;
        *(float2*)(ot + (r0 + 8) * EE + col) = o1;
    }
}

// ---------------------------------------------------------------------------
extern "C" void kernel_launch(void* const* d_in, const int* in_sizes, int n_in,
                              void* d_out, int out_size)
{
    const float* x     = (const float*)d_in[0];
    const float* w_in  = (const float*)d_in[1];
    const float* b_in  = (const float*)d_in[2];
    const float* w_out = (const float*)d_in[3];
    const float* b_out = (const float*)d_in[4];
    float* out = (float*)d_out;

    float *xt, *wit, *wot, *at;
    __nv_bfloat16 *qkh, *qkl;
    cudaGetSymbolAddress((void**)&xt,  g_x_t);
    cudaGetSymbolAddress((void**)&wit, g_wi_t);
    cudaGetSymbolAddress((void**)&wot, g_wo_t);
    cudaGetSymbolAddress((void**)&at,  g_a_t);
    cudaGetSymbolAddress((void**)&qkh, g_qkv_hi);
    cudaGetSymbolAddress((void**)&qkl, g_qkv_lo);

    cudaFuncSetAttribute(gemm_tf32<true>,  cudaFuncAttributeMaxDynamicSharedMemorySize, GEMM_SMEM);
    cudaFuncSetAttribute(gemm_tf32<false>, cudaFuncAttributeMaxDynamicSharedMemorySize, GEMM_SMEM);
    cudaFuncSetAttribute(attn_mma,         cudaFuncAttributeMaxDynamicSharedMemorySize, ATTN_SMEM);

    // 1) round inputs to tf32
    round_kernel<<<(MM * EE / 4 + 255) / 256, 256>>>(x,     xt,  MM * EE / 4);
    round_kernel<<<(E3 * EE / 4 + 255) / 256, 256>>>(w_in,  wit, E3 * EE / 4);
    round_kernel<<<(EE * EE / 4 + 255) / 256, 256>>>(w_out, wot, EE * EE / 4);

    // 2) QKV projection (tf32 single-pass) -> split bf16 qkv for attention
    gemm_tf32<true><<<dim3(E3 / 128, MM / 128), 256, GEMM_SMEM>>>(
        xt, wit, b_in, nullptr, qkh, qkl, E3, EE);

    // 3) attention (bf16 3-term) -> tf32-rounded fp32 output
    attn_mma<<<dim3(SS / 64, HH, BB), 128, ATTN_SMEM>>>(qkh, qkl, at);

    // 4) out projection (tf32 single-pass) -> fp32 final
    gemm_tf32<false><<<dim3(EE / 128, MM / 128), 256, GEMM_SMEM>>>(
        at, wot, b_out, out, nullptr, nullptr, EE, EE);
}

// round 9
// speedup vs baseline: 3.8776x; 1.0592x over previous
#include <cuda_runtime.h>
#include <cuda_bf16.h>
#include <math.h>
#include <stdint.h>

#define BB   2
#define SS   2048
#define EE   1024
#define E3   3072
#define HH   16
#define DH   64
#define MM   (BB*SS)   // 4096

// ---------------------------------------------------------------------------
// Scratch (__device__ globals; no allocs allowed)
// ---------------------------------------------------------------------------
__device__ float g_x_t [MM * EE];
__device__ float g_wi_t[E3 * EE];
__device__ float g_wo_t[EE * EE];
__device__ float g_a_t [MM * EE];
__device__ __nv_bfloat16 g_qkv_hi[MM * E3], g_qkv_lo[MM * E3];

// ---------------------------------------------------------------------------
// helpers
// ---------------------------------------------------------------------------
__device__ __forceinline__ void mma16816(float* d, const uint32_t* a, const uint32_t* b) {
    asm volatile(
        "mma.sync.aligned.m16n8k16.row.col.f32.bf16.bf16.f32 "
        "{%0,%1,%2,%3}, {%4,%5,%6,%7}, {%8,%9}, {%0,%1,%2,%3};"
        : "+f"(d[0]), "+f"(d[1]), "+f"(d[2]), "+f"(d[3])
        : "r"(a[0]), "r"(a[1]), "r"(a[2]), "r"(a[3]), "r"(b[0]), "r"(b[1]));
}
__device__ __forceinline__ void mma_tf32(float* d, const uint32_t* a, const uint32_t* b) {
    asm volatile(
        "mma.sync.aligned.m16n8k8.row.col.f32.tf32.tf32.f32 "
        "{%0,%1,%2,%3}, {%4,%5,%6,%7}, {%8,%9}, {%0,%1,%2,%3};"
        : "+f"(d[0]), "+f"(d[1]), "+f"(d[2]), "+f"(d[3])
        : "r"(a[0]), "r"(a[1]), "r"(a[2]), "r"(a[3]), "r"(b[0]), "r"(b[1]));
}
__device__ __forceinline__ void ldsm4(uint32_t* r, uint32_t saddr) {
    asm volatile("ldmatrix.sync.aligned.m8n8.x4.shared.b16 {%0,%1,%2,%3}, [%4];"
        : "=r"(r[0]), "=r"(r[1]), "=r"(r[2]), "=r"(r[3]) : "r"(saddr));
}
__device__ __forceinline__ void ldsm4t(uint32_t* r, uint32_t saddr) {
    asm volatile("ldmatrix.sync.aligned.m8n8.x4.trans.shared.b16 {%0,%1,%2,%3}, [%4];"
        : "=r"(r[0]), "=r"(r[1]), "=r"(r[2]), "=r"(r[3]) : "r"(saddr));
}
__device__ __forceinline__ uint32_t s2u(const void* p) {
    return (uint32_t)__cvta_generic_to_shared(p);
}
__device__ __forceinline__ uint32_t pack2(__nv_bfloat16 a, __nv_bfloat16 b) {
    __nv_bfloat162 t(a, b);
    return *(uint32_t*)&t;
}
__device__ __forceinline__ void cpa16(uint32_t s, const void* g) {
    asm volatile("cp.async.cg.shared.global [%0], [%1], 16;" :: "r"(s), "l"(g));
}
#define CPA_COMMIT()  asm volatile("cp.async.commit_group;" ::: "memory")
#define CPA_WAIT(n)   asm volatile("cp.async.wait_group %0;" :: "n"(n) : "memory")

__device__ __forceinline__ void split1(float v, __nv_bfloat16& h, __nv_bfloat16& l) {
    h = __float2bfloat16(v);
    l = __float2bfloat16(v - __bfloat162float(h));
}
__device__ __forceinline__ float to_tf32(float v) {
    uint32_t r;
    asm("cvt.rna.tf32.f32 %0, %1;" : "=r"(r) : "f"(v));
    return __uint_as_float(r);
}

// ---------------------------------------------------------------------------
// fp32 -> tf32-rounded fp32
// ---------------------------------------------------------------------------
__global__ __launch_bounds__(256) void round_kernel(
    const float* __restrict__ in, float* __restrict__ outp, int n4)
{
    int i = blockIdx.x * blockDim.x + threadIdx.x;
    if (i >= n4) return;
    float4 v = ((const float4*)in)[i];
    v.x = to_tf32(v.x); v.y = to_tf32(v.y);
    v.z = to_tf32(v.z); v.w = to_tf32(v.w);
    ((float4*)outp)[i] = v;
}

// ---------------------------------------------------------------------------
// Single-pass TF32 GEMM, 3-stage cp.async pipeline, one sync/iter.
// BM=BN=128, BK=32, 256 thr (2m x 4n warps), warp tile 64x32.
// ---------------------------------------------------------------------------
#define GP 36
#define GT (128 * GP)
#define GSTGW (2 * GT)
#define GEMM_SMEM (3 * GSTGW * 4)          // 110592 bytes

template<bool SPLIT>
__global__ __launch_bounds__(256, 2) void gemm_tf32(
    const float* __restrict__ A, const float* __restrict__ Bw,
    const float* __restrict__ bias, float* __restrict__ C,
    __nv_bfloat16* __restrict__ Ch, __nv_bfloat16* __restrict__ Cl,
    int N, int K)
{
    extern __shared__ __align__(16) float dsm[];

    const int tid  = threadIdx.x;
    const int wid  = tid >> 5, lane = tid & 31;
    const int wm   = wid & 1, wn = wid >> 1;
    const int g    = lane >> 2, ti = lane & 3;
    const int m0   = blockIdx.y * 128, n0 = blockIdx.x * 128;

    const int a_row = lane & 15;
    const int a_csel = (lane >> 4) * 4;
    const int b_row = (lane & 7) + ((lane >> 4) * 8);
    const int b_csel = ((lane >> 3) & 1) * 4;

    auto issue = [&](int kc, int s) {
        float* base = dsm + s * GSTGW;
        const int kb = kc * 32;
        #pragma unroll
        for (int i = 0; i < 4; i++) {
            int idx = tid + i * 256;
            int row = idx >> 3;
            int seg = (idx & 7) * 4;
            int off = row * GP + seg;
            cpa16(s2u(base + off),      A  + (size_t)(m0 + row) * K + kb + seg);
            cpa16(s2u(base + GT + off), Bw + (size_t)(n0 + row) * K + kb + seg);
        }
    };

    float acc[4][4][4] = {};
    const int nchunk = K >> 5;

    issue(0, 0); CPA_COMMIT();
    issue(1, 1); CPA_COMMIT();

    int stage = 0;
    for (int kc = 0; kc < nchunk; kc++) {
        if (kc + 1 < nchunk) { CPA_WAIT(1); } else { CPA_WAIT(0); }
        __syncthreads();

        const float* sA = dsm + stage * GSTGW;
        const float* sB = sA + GT;

        #pragma unroll
        for (int ks = 0; ks < 4; ks++) {
            const int k0 = ks * 8;
            uint32_t b[4][2];
            #pragma unroll
            for (int nfp = 0; nfp < 2; nfp++) {
                int r = wn * 32 + nfp * 16 + b_row;
                uint32_t t[4];
                ldsm4(t, s2u(&sB[r * GP + k0 + b_csel]));
                b[2*nfp][0] = t[0]; b[2*nfp][1] = t[1];
                b[2*nfp+1][0] = t[2]; b[2*nfp+1][1] = t[3];
            }
            #pragma unroll
            for (int mf = 0; mf < 4; mf++) {
                int r = wm * 64 + mf * 16 + a_row;
                uint32_t a[4];
                ldsm4(a, s2u(&sA[r * GP + k0 + a_csel]));
                #pragma unroll
                for (int nf = 0; nf < 4; nf++)
                    mma_tf32(acc[mf][nf], a, b[nf]);
            }
        }

        if (kc + 2 < nchunk) {
            int s2 = stage + 2; if (s2 >= 3) s2 -= 3;
            issue(kc + 2, s2); CPA_COMMIT();
        }
        if (++stage == 3) stage = 0;
    }

    #pragma unroll
    for (int mf = 0; mf < 4; mf++) {
        int r0 = m0 + wm * 64 + mf * 16 + g;
        #pragma unroll
        for (int nf = 0; nf < 4; nf++) {
            int col = n0 + wn * 32 + nf * 8 + ti * 2;
            float2 bv = *(const float2*)(bias + col);
            float o00 = acc[mf][nf][0] + bv.x, o01 = acc[mf][nf][1] + bv.y;
            float o10 = acc[mf][nf][2] + bv.x, o11 = acc[mf][nf][3] + bv.y;
            if (SPLIT) {
                __nv_bfloat16 h0, h1, l0b, l1b;
                split1(o00, h0, l0b); split1(o01, h1, l1b);
                *(__nv_bfloat162*)(Ch + (size_t)r0 * N + col) = __nv_bfloat162(h0, h1);
                *(__nv_bfloat162*)(Cl + (size_t)r0 * N + col) = __nv_bfloat162(l0b, l1b);
                split1(o10, h0, l0b); split1(o11, h1, l1b);
                *(__nv_bfloat162*)(Ch + (size_t)(r0 + 8) * N + col) = __nv_bfloat162(h0, h1);
                *(__nv_bfloat162*)(Cl + (size_t)(r0 + 8) * N + col) = __nv_bfloat162(l0b, l1b);
            } else {
                *(float2*)(C + (size_t)r0 * N + col)       = make_float2(o00, o01);
                *(float2*)(C + (size_t)(r0 + 8) * N + col) = make_float2(o10, o11);
            }
        }
    }
}

// ---------------------------------------------------------------------------
// Tensor-core flash attention, split-bf16, q-tile=128 (256 thr, 8 warps),
// 3-stage cp.async KV pipeline, one sync/iter. Per-warp math identical to R8.
// ---------------------------------------------------------------------------
#define APAD 72
#define AARR (64 * APAD)
#define ASTG (4 * AARR)
#define ATTN_SMEM (3 * ASTG * 2)           // 110592 bytes
#define NT (SS / 64)

__global__ __launch_bounds__(256, 2) void attn_mma(
    const __nv_bfloat16* __restrict__ qg_h, const __nv_bfloat16* __restrict__ qg_l,
    float* __restrict__ ot)
{
    extern __shared__ __align__(16) __nv_bfloat16 adsm[];

    const int tid = threadIdx.x;
    const int wid = tid >> 5, lane = tid & 31;
    const int g = lane >> 2, ti = lane & 3;
    const int qt = blockIdx.x, h = blockIdx.y, b = blockIdx.z;
    const int h64 = h * DH;
    const size_t qrow0 = (size_t)(b * SS + qt * 128);

    const int lrow = tid >> 3;           // 0..31
    const int lc8  = (tid & 7) * 8;

    const int b_i = lane & 7, b_seg = lane >> 3;
    const int b_rofs = (b_seg >> 1) * 8 + b_i, b_cofs = (b_seg & 1) * 8;

    auto issue = [&](int kt, int s) {
        __nv_bfloat16* base = adsm + s * ASTG;
        const size_t krow0 = (size_t)(b * SS + kt * 64);
        #pragma unroll
        for (int i = 0; i < 2; i++) {
            int row = lrow + i * 32;
            int off = row * APAD + lc8;
            size_t gk = (krow0 + row) * E3 +     EE + h64 + lc8;
            size_t gv = (krow0 + row) * E3 + 2 * EE + h64 + lc8;
            cpa16(s2u(base + off),            qg_h + gk);
            cpa16(s2u(base + AARR + off),     qg_l + gk);
            cpa16(s2u(base + 2 * AARR + off), qg_h + gv);
            cpa16(s2u(base + 3 * AARR + off), qg_l + gv);
        }
    };

    issue(0, 0); CPA_COMMIT();
    issue(1, 1); CPA_COMMIT();

    // stage Q (128 rows) into stage-2 slots: hi -> Kh+Kl region, lo -> Vh+Vl
    {
        __nv_bfloat16* qbh = adsm + 2 * ASTG;
        __nv_bfloat16* qbl = adsm + 2 * ASTG + 2 * AARR;
        #pragma unroll
        for (int i = 0; i < 4; i++) {
            int row = lrow + i * 32;
            size_t go = (qrow0 + row) * E3 + h64 + lc8;
            *(uint4*)(qbh + row * APAD + lc8) = *(const uint4*)(qg_h + go);
            *(uint4*)(qbl + row * APAD + lc8) = *(const uint4*)(qg_l + go);
        }
    }
    __syncthreads();
    uint32_t qh[4][4], ql[4][4];
    {
        const __nv_bfloat16* qbh = adsm + 2 * ASTG;
        const __nv_bfloat16* qbl = adsm + 2 * ASTG + 2 * AARR;
        const int a_r = lane & 15, a_c = (lane >> 4) * 8;
        #pragma unroll
        for (int ks = 0; ks < 4; ks++) {
            int k16 = ks * 16;
            int r = wid * 16 + a_r;
            ldsm4(qh[ks], s2u(&qbh[r * APAD + k16 + a_c]));
            ldsm4(ql[ks], s2u(&qbl[r * APAD + k16 + a_c]));
        }
    }
    __syncthreads();   // all warps done reading stage-2 Q before iter-0 issues into it

    float m0 = -1e30f, m1 = -1e30f, l0 = 0.f, l1 = 0.f;
    float accO[8][4] = {};
    const float scale = 0.125f;

    int stage = 0;
    for (int kt = 0; kt < NT; kt++) {
        if (kt + 1 < NT) { CPA_WAIT(1); } else { CPA_WAIT(0); }
        __syncthreads();

        const __nv_bfloat16* sKh = adsm + stage * ASTG;
        const __nv_bfloat16* sKl = sKh + AARR;
        const __nv_bfloat16* sVh = sKh + 2 * AARR;
        const __nv_bfloat16* sVl = sKh + 3 * AARR;

        // S = Q K^T (3-term split)
        float sacc[8][4] = {};
        #pragma unroll
        for (int ks = 0; ks < 4; ks++) {
            int k16 = ks * 16;
            #pragma unroll
            for (int nfp = 0; nfp < 4; nfp++) {
                int r = nfp * 16 + b_rofs;
                uint32_t th[4], tl[4];
                ldsm4(th, s2u(&sKh[r * APAD + k16 + b_cofs]));
                ldsm4(tl, s2u(&sKl[r * APAD + k16 + b_cofs]));
                mma16816(sacc[2*nfp],     qh[ks], th);
                mma16816(sacc[2*nfp],     qh[ks], tl);
                mma16816(sacc[2*nfp],     ql[ks], th);
                mma16816(sacc[2*nfp + 1], qh[ks], th + 2);
                mma16816(sacc[2*nfp + 1], qh[ks], tl + 2);
                mma16816(sacc[2*nfp + 1], ql[ks], th + 2);
            }
        }

        // online softmax
        float mx0 = -1e30f, mx1 = -1e30f;
        #pragma unroll
        for (int nf = 0; nf < 8; nf++) {
            sacc[nf][0] *= scale; sacc[nf][1] *= scale;
            sacc[nf][2] *= scale; sacc[nf][3] *= scale;
            mx0 = fmaxf(mx0, fmaxf(sacc[nf][0], sacc[nf][1]));
            mx1 = fmaxf(mx1, fmaxf(sacc[nf][2], sacc[nf][3]));
        }
        mx0 = fmaxf(mx0, __shfl_xor_sync(0xffffffffu, mx0, 1));
        mx0 = fmaxf(mx0, __shfl_xor_sync(0xffffffffu, mx0, 2));
        mx1 = fmaxf(mx1, __shfl_xor_sync(0xffffffffu, mx1, 1));
        mx1 = fmaxf(mx1, __shfl_xor_sync(0xffffffffu, mx1, 2));
        float mn0 = fmaxf(m0, mx0), mn1 = fmaxf(m1, mx1);
        float c0 = __expf(m0 - mn0), c1 = __expf(m1 - mn1);
        float rs0 = 0.f, rs1 = 0.f;
        #pragma unroll
        for (int nf = 0; nf < 8; nf++) {
            sacc[nf][0] = __expf(sacc[nf][0] - mn0);
            sacc[nf][1] = __expf(sacc[nf][1] - mn0);
            sacc[nf][2] = __expf(sacc[nf][2] - mn1);
            sacc[nf][3] = __expf(sacc[nf][3] - mn1);
            rs0 += sacc[nf][0] + sacc[nf][1];
            rs1 += sacc[nf][2] + sacc[nf][3];
        }
        rs0 += __shfl_xor_sync(0xffffffffu, rs0, 1);
        rs0 += __shfl_xor_sync(0xffffffffu, rs0, 2);
        rs1 += __shfl_xor_sync(0xffffffffu, rs1, 1);
        rs1 += __shfl_xor_sync(0xffffffffu, rs1, 2);
        l0 = l0 * c0 + rs0; l1 = l1 * c1 + rs1;
        m0 = mn0; m1 = mn1;
        #pragma unroll
        for (int nf = 0; nf < 8; nf++) {
            accO[nf][0] *= c0; accO[nf][1] *= c0;
            accO[nf][2] *= c1; accO[nf][3] *= c1;
        }

        // O += P V
        #pragma unroll
        for (int ks2 = 0; ks2 < 4; ks2++) {
            const int f0 = 2 * ks2, f1 = 2 * ks2 + 1;
            __nv_bfloat16 ph[8], plo[8];
            split1(sacc[f0][0], ph[0], plo[0]); split1(sacc[f0][1], ph[1], plo[1]);
            split1(sacc[f0][2], ph[2], plo[2]); split1(sacc[f0][3], ph[3], plo[3]);
            split1(sacc[f1][0], ph[4], plo[4]); split1(sacc[f1][1], ph[5], plo[5]);
            split1(sacc[f1][2], ph[6], plo[6]); split1(sacc[f1][3], ph[7], plo[7]);
            uint32_t pa[4], pl[4];
            pa[0] = pack2(ph[0], ph[1]);  pa[1] = pack2(ph[2], ph[3]);
            pa[2] = pack2(ph[4], ph[5]);  pa[3] = pack2(ph[6], ph[7]);
            pl[0] = pack2(plo[0], plo[1]); pl[1] = pack2(plo[2], plo[3]);
            pl[2] = pack2(plo[4], plo[5]); pl[3] = pack2(plo[6], plo[7]);

            const int k16 = ks2 * 16;
            const int quad = lane >> 3;
            const int vrow = k16 + (lane & 7) + (quad & 1) * 8;
            #pragma unroll
            for (int np = 0; np < 4; np++) {
                const int vcol = np * 16 + (quad >> 1) * 8;
                uint32_t vb[4], vlb[4];
                ldsm4t(vb,  s2u(&sVh[vrow * APAD + vcol]));
                ldsm4t(vlb, s2u(&sVl[vrow * APAD + vcol]));
                mma16816(accO[np*2],     pa, vb);
                mma16816(accO[np*2],     pa, vlb);
                mma16816(accO[np*2],     pl, vb);
                mma16816(accO[np*2 + 1], pa, vb + 2);
                mma16816(accO[np*2 + 1], pa, vlb + 2);
                mma16816(accO[np*2 + 1], pl, vb + 2);
            }
        }

        if (kt + 2 < NT) {
            int s2 = stage + 2; if (s2 >= 3) s2 -= 3;
            issue(kt + 2, s2); CPA_COMMIT();
        }
        if (++stage == 3) stage = 0;
    }

    // epilogue: normalize, round to tf32, store fp32
    const float inv0 = 1.0f / l0, inv1 = 1.0f / l1;
    const size_t r0 = qrow0 + wid * 16 + g;
    #pragma unroll
    for (int nf = 0; nf < 8; nf++) {
        int col = h64 + nf * 8 + 2 * ti;
        float2 o0, o1;
        o0.x = to_tf32(accO[nf][0] * inv0); o0.y = to_tf32(accO[nf][1] * inv0);
        o1.x = to_tf32(accO[nf][2] * inv1); o1.y = to_tf32(accO[nf][3] * inv1);
        *(float2*)(ot + r0 * EE + col)       = o0;
        *(float2*)(ot + (r0 + 8) * EE + col) = o1;
    }
}

// ---------------------------------------------------------------------------
extern "C" void kernel_launch(void* const* d_in, const int* in_sizes, int n_in,
                              void* d_out, int out_size)
{
    const float* x     = (const float*)d_in[0];
    const float* w_in  = (const float*)d_in[1];
    const float* b_in  = (const float*)d_in[2];
    const float* w_out = (const float*)d_in[3];
    const float* b_out = (const float*)d_in[4];
    float* out = (float*)d_out;

    float *xt, *wit, *wot, *at;
    __nv_bfloat16 *qkh, *qkl;
    cudaGetSymbolAddress((void**)&xt,  g_x_t);
    cudaGetSymbolAddress((void**)&wit, g_wi_t);
    cudaGetSymbolAddress((void**)&wot, g_wo_t);
    cudaGetSymbolAddress((void**)&at,  g_a_t);
    cudaGetSymbolAddress((void**)&qkh, g_qkv_hi);
    cudaGetSymbolAddress((void**)&qkl, g_qkv_lo);

    cudaFuncSetAttribute(gemm_tf32<true>,  cudaFuncAttributeMaxDynamicSharedMemorySize, GEMM_SMEM);
    cudaFuncSetAttribute(gemm_tf32<false>, cudaFuncAttributeMaxDynamicSharedMemorySize, GEMM_SMEM);
    cudaFuncSetAttribute(attn_mma,         cudaFuncAttributeMaxDynamicSharedMemorySize, ATTN_SMEM);

    round_kernel<<<(MM * EE / 4 + 255) / 256, 256>>>(x,     xt,  MM * EE / 4);
    round_kernel<<<(E3 * EE / 4 + 255) / 256, 256>>>(w_in,  wit, E3 * EE / 4);
    round_kernel<<<(EE * EE / 4 + 255) / 256, 256>>>(w_out, wot, EE * EE / 4);

    gemm_tf32<true><<<dim3(E3 / 128, MM / 128), 256, GEMM_SMEM>>>(
        xt, wit, b_in, nullptr, qkh, qkl, E3, EE);

    attn_mma<<<dim3(SS / 128, HH, BB), 256, ATTN_SMEM>>>(qkh, qkl, at);

    gemm_tf32<false><<<dim3(EE / 128, MM / 128), 256, GEMM_SMEM>>>(
        at, wot, b_out, out, nullptr, nullptr, EE, EE);
}